// round 1
// baseline (speedup 1.0000x reference)
#include <cuda_runtime.h>
#include <math.h>

// Problem dims (fixed by reference)
#define BB   8
#define SS   256
#define HH   768
#define NLL  12
#define NHH  12
#define FFF  3072
#define CC   9
#define DHH  64
#define TOK  (BB*SS)   // 2048

// -------- scratch (static device globals; no runtime alloc) --------
__device__ float g_h  [TOK*HH];
__device__ float g_q  [TOK*HH];
__device__ float g_k  [TOK*HH];
__device__ float g_v  [TOK*HH];
__device__ float g_ctx[TOK*HH];
__device__ float g_t1 [TOK*HH];
__device__ float g_ffn[TOK*FFF];
__device__ float g_em [TOK*CC];

// =================== embed + LN ===================
__global__ void embed_ln_kernel(const int* __restrict__ x,
                                const float* __restrict__ we,
                                const float* __restrict__ pe,
                                const float* __restrict__ te,
                                const float* __restrict__ lw,
                                const float* __restrict__ lb) {
    int t = blockIdx.x;          // token 0..2047
    int s = t % SS;
    int tid = threadIdx.x;       // 256 threads
    int wid = x[t];

    float vals[3];
    float sum = 0.f, sq = 0.f;
#pragma unroll
    for (int r = 0; r < 3; r++) {
        int i = tid + r * 256;
        float v = we[(size_t)wid * HH + i] + pe[s * HH + i] + te[i];
        vals[r] = v; sum += v; sq += v * v;
    }
    __shared__ float red[256], red2[256];
    red[tid] = sum; red2[tid] = sq; __syncthreads();
    for (int off = 128; off > 0; off >>= 1) {
        if (tid < off) { red[tid] += red[tid + off]; red2[tid] += red2[tid + off]; }
        __syncthreads();
    }
    float m    = red[0] * (1.f / HH);
    float var  = red2[0] * (1.f / HH) - m * m;
    float rstd = rsqrtf(var + 1e-12f);
#pragma unroll
    for (int r = 0; r < 3; r++) {
        int i = tid + r * 256;
        g_h[(size_t)t * HH + i] = (vals[r] - m) * rstd * lw[i] + lb[i];
    }
}

// =================== residual add + LN (in-place into g_h) ===================
__global__ void resid_ln_kernel(const float* __restrict__ add,
                                const float* __restrict__ lw,
                                const float* __restrict__ lb) {
    int t = blockIdx.x;
    int tid = threadIdx.x;
    float vals[3];
    float sum = 0.f, sq = 0.f;
#pragma unroll
    for (int r = 0; r < 3; r++) {
        int i = tid + r * 256;
        float v = g_h[(size_t)t * HH + i] + add[(size_t)t * HH + i];
        vals[r] = v; sum += v; sq += v * v;
    }
    __shared__ float red[256], red2[256];
    red[tid] = sum; red2[tid] = sq; __syncthreads();
    for (int off = 128; off > 0; off >>= 1) {
        if (tid < off) { red[tid] += red[tid + off]; red2[tid] += red2[tid + off]; }
        __syncthreads();
    }
    float m    = red[0] * (1.f / HH);
    float var  = red2[0] * (1.f / HH) - m * m;
    float rstd = rsqrtf(var + 1e-12f);
#pragma unroll
    for (int r = 0; r < 3; r++) {
        int i = tid + r * 256;
        g_h[(size_t)t * HH + i] = (vals[r] - m) * rstd * lw[i] + lb[i];
    }
}

// =================== SGEMM: C = A(MxK) @ W(KxN) + bias, optional gelu ===================
#define BM 128
#define BN 64
#define BK 8

__device__ __forceinline__ float gelu_tanh(float v) {
    // jax.nn.gelu default (approximate=True)
    float c = 0.7978845608028654f * (v + 0.044715f * v * v * v);
    return 0.5f * v * (1.f + tanhf(c));
}

__global__ __launch_bounds__(256)
void sgemm_bias(const float* __restrict__ A, const float* __restrict__ W,
                const float* __restrict__ bias, float* __restrict__ Cg,
                int M, int N, int K, int act) {
    __shared__ float As[BK][BM];     // transposed A tile
    __shared__ float Bs[BK][BN];

    int tid = threadIdx.x;
    int tx = tid & 15;               // 0..15 -> 4 cols each
    int ty = tid >> 4;               // 0..15 -> 8 rows each
    int rowBase = blockIdx.y * BM;
    int colBase = blockIdx.x * BN;

    int arow = tid >> 1;             // 0..127
    int acol = (tid & 1) * 4;        // 0 or 4
    int brow = tid >> 4;             // 0..15 (only <8 used via tid<128)
    int bcol = (tid & 15) * 4;

    float acc[8][4];
#pragma unroll
    for (int i = 0; i < 8; i++)
#pragma unroll
        for (int j = 0; j < 4; j++) acc[i][j] = 0.f;

    for (int k0 = 0; k0 < K; k0 += BK) {
        float4 av = *(const float4*)&A[(size_t)(rowBase + arow) * K + k0 + acol];
        As[acol + 0][arow] = av.x;
        As[acol + 1][arow] = av.y;
        As[acol + 2][arow] = av.z;
        As[acol + 3][arow] = av.w;
        if (tid < 128) {
            float4 bv = *(const float4*)&W[(size_t)(k0 + brow) * N + colBase + bcol];
            *(float4*)&Bs[brow][bcol] = bv;
        }
        __syncthreads();
#pragma unroll
        for (int kk = 0; kk < BK; kk++) {
            float4 a0 = *(const float4*)&As[kk][ty * 8];
            float4 a1 = *(const float4*)&As[kk][ty * 8 + 4];
            float4 bv = *(const float4*)&Bs[kk][tx * 4];
            float a[8] = {a0.x, a0.y, a0.z, a0.w, a1.x, a1.y, a1.z, a1.w};
            float b[4] = {bv.x, bv.y, bv.z, bv.w};
#pragma unroll
            for (int i = 0; i < 8; i++)
#pragma unroll
                for (int j = 0; j < 4; j++)
                    acc[i][j] += a[i] * b[j];
        }
        __syncthreads();
    }

#pragma unroll
    for (int i = 0; i < 8; i++) {
        int r = rowBase + ty * 8 + i;
#pragma unroll
        for (int j = 0; j < 4; j++) {
            int c = colBase + tx * 4 + j;
            float v = acc[i][j] + bias[c];
            if (act) v = gelu_tanh(v);
            Cg[(size_t)r * N + c] = v;
        }
    }
}

// =================== fused attention: scores -> softmax -> ctx ===================
__global__ void attn_kernel() {
    int qi = blockIdx.x;    // 0..255
    int hh = blockIdx.y;    // 0..11
    int b  = blockIdx.z;    // 0..7
    int tid = threadIdx.x;  // 256

    __shared__ float qv[DHH];
    __shared__ float sc[SS];
    __shared__ float red[256];

    size_t base = (size_t)(b * SS) * HH + hh * DHH;
    if (tid < DHH) qv[tid] = g_q[base + (size_t)qi * HH + tid];
    __syncthreads();

    // scores
    {
        const float* Kr = &g_k[base + (size_t)tid * HH];
        float s = 0.f;
#pragma unroll
        for (int d = 0; d < DHH; d++) s += qv[d] * Kr[d];
        sc[tid] = s * 0.125f;   // 1/sqrt(64)
    }
    __syncthreads();

    // max reduce
    red[tid] = sc[tid]; __syncthreads();
    for (int off = 128; off > 0; off >>= 1) {
        if (tid < off) red[tid] = fmaxf(red[tid], red[tid + off]);
        __syncthreads();
    }
    float bmax = red[0];
    __syncthreads();

    float e = __expf(sc[tid] - bmax);
    sc[tid] = e;
    red[tid] = e; __syncthreads();
    for (int off = 128; off > 0; off >>= 1) {
        if (tid < off) red[tid] += red[tid + off];
        __syncthreads();
    }
    float inv = 1.f / red[0];
    __syncthreads();

    // ctx: thread d accumulates over k
    if (tid < DHH) {
        int d = tid;
        float acc = 0.f;
        const float* Vb = &g_v[base + d];
        for (int ki = 0; ki < SS; ki++)
            acc += sc[ki] * Vb[(size_t)ki * HH];
        g_ctx[base + (size_t)qi * HH + d] = acc * inv;
    }
}

// =================== emissions: (TOK,H) @ (H,C) + b ===================
__global__ void emissions_kernel(const float* __restrict__ cw,
                                 const float* __restrict__ cb) {
    int t = blockIdx.x;
    int tid = threadIdx.x;   // 256
    float part[CC];
#pragma unroll
    for (int c = 0; c < CC; c++) part[c] = 0.f;
    for (int k = tid; k < HH; k += 256) {
        float hv = g_h[(size_t)t * HH + k];
        const float* wr = cw + (size_t)k * CC;
#pragma unroll
        for (int c = 0; c < CC; c++) part[c] += hv * wr[c];
    }
#pragma unroll
    for (int c = 0; c < CC; c++)
        for (int off = 16; off > 0; off >>= 1)
            part[c] += __shfl_down_sync(0xffffffffu, part[c], off);

    __shared__ float wred[8][CC];
    int lane = tid & 31, w = tid >> 5;
    if (lane == 0)
#pragma unroll
        for (int c = 0; c < CC; c++) wred[w][c] = part[c];
    __syncthreads();
    if (tid < CC) {
        float s = cb[tid];
#pragma unroll
        for (int ww = 0; ww < 8; ww++) s += wred[ww][tid];
        g_em[(size_t)t * CC + tid] = s;
    }
}

// =================== CRF loss (single block) ===================
__global__ void crf_kernel(const int* __restrict__ target,
                           const float* __restrict__ cstart,
                           const float* __restrict__ cend,
                           const float* __restrict__ ctrans,
                           float* __restrict__ out) {
    __shared__ float alpha[BB][CC];
    __shared__ float trans[CC][CC];
    __shared__ float den[BB], num[BB];
    int tid = threadIdx.x;   // 128

    if (tid < CC * CC) trans[tid / CC][tid % CC] = ctrans[tid];
    __syncthreads();

    int b = tid / CC, j = tid % CC;
    bool act = (tid < BB * CC);
    if (act) alpha[b][j] = cstart[j] + g_em[(size_t)(b * SS) * CC + j];
    __syncthreads();

    for (int s = 1; s < SS; s++) {
        float nv = 0.f;
        if (act) {
            float m = -1e30f;
#pragma unroll
            for (int i = 0; i < CC; i++) m = fmaxf(m, alpha[b][i] + trans[i][j]);
            float sum = 0.f;
#pragma unroll
            for (int i = 0; i < CC; i++) sum += __expf(alpha[b][i] + trans[i][j] - m);
            nv = m + __logf(sum) + g_em[(size_t)(b * SS + s) * CC + j];
            if (!(target[b * SS + s] > -1)) nv = alpha[b][j];
        }
        __syncthreads();
        if (act) alpha[b][j] = nv;
        __syncthreads();
    }

    if (act && j == 0) {
        // denominator
        float m = -1e30f;
#pragma unroll
        for (int jj = 0; jj < CC; jj++) m = fmaxf(m, alpha[b][jj] + cend[jj]);
        float sum = 0.f;
#pragma unroll
        for (int jj = 0; jj < CC; jj++) sum += __expf(alpha[b][jj] + cend[jj] - m);
        den[b] = m + __logf(sum);

        // numerator
        const int* tb = target + b * SS;
        int cnt = 0;
        for (int s = 0; s < SS; s++) cnt += (tb[s] > -1) ? 1 : 0;
        int send = cnt - 1;
        int t0 = tb[0] < 0 ? 0 : tb[0];
        float nu = cstart[t0] + g_em[(size_t)(b * SS) * CC + t0];
        for (int s = 1; s < SS; s++) {
            int ts = tb[s], tp = tb[s - 1];
            float mk = (ts > -1) ? 1.f : 0.f;
            int tsc = ts < 0 ? 0 : ts, tpc = tp < 0 ? 0 : tp;
            nu += mk * (trans[tpc][tsc] + g_em[(size_t)(b * SS + s) * CC + tsc]);
        }
        int last = tb[send < 0 ? 0 : send];
        nu += cend[last < 0 ? 0 : last];
        num[b] = nu;
    }
    __syncthreads();
    if (tid == 0) {
        float L = 0.f;
        for (int bb = 0; bb < BB; bb++) L += num[bb] - den[bb];
        out[0] = -L / BB;
    }
}

// =================== launch ===================
extern "C" void kernel_launch(void* const* d_in, const int* in_sizes, int n_in,
                              void* d_out, int out_size) {
    const int*   x          = (const int*)  d_in[0];
    const int*   target     = (const int*)  d_in[1];
    const float* word_emb   = (const float*)d_in[2];
    const float* pos_emb    = (const float*)d_in[3];
    const float* type_emb   = (const float*)d_in[4];
    const float* emb_ln_w   = (const float*)d_in[5];
    const float* emb_ln_b   = (const float*)d_in[6];
    const float* qkv_w      = (const float*)d_in[7];
    const float* qkv_b      = (const float*)d_in[8];
    const float* attn_out_w = (const float*)d_in[9];
    const float* attn_out_b = (const float*)d_in[10];
    const float* attn_ln_w  = (const float*)d_in[11];
    const float* attn_ln_b  = (const float*)d_in[12];
    const float* ffn_w1     = (const float*)d_in[13];
    const float* ffn_b1     = (const float*)d_in[14];
    const float* ffn_w2     = (const float*)d_in[15];
    const float* ffn_b2     = (const float*)d_in[16];
    const float* ffn_ln_w   = (const float*)d_in[17];
    const float* ffn_ln_b   = (const float*)d_in[18];
    const float* cls_w      = (const float*)d_in[19];
    const float* cls_b      = (const float*)d_in[20];
    const float* crf_start  = (const float*)d_in[21];
    const float* crf_end    = (const float*)d_in[22];
    const float* crf_trans  = (const float*)d_in[23];
    float* out = (float*)d_out;

    float *ph, *pq, *pk, *pv, *pctx, *pt1, *pffn;
    cudaGetSymbolAddress((void**)&ph,   g_h);
    cudaGetSymbolAddress((void**)&pq,   g_q);
    cudaGetSymbolAddress((void**)&pk,   g_k);
    cudaGetSymbolAddress((void**)&pv,   g_v);
    cudaGetSymbolAddress((void**)&pctx, g_ctx);
    cudaGetSymbolAddress((void**)&pt1,  g_t1);
    cudaGetSymbolAddress((void**)&pffn, g_ffn);

    embed_ln_kernel<<<TOK, 256>>>(x, word_emb, pos_emb, type_emb, emb_ln_w, emb_ln_b);

    dim3 gH(HH / BN, TOK / BM);    // (12, 16)
    dim3 gF(FFF / BN, TOK / BM);   // (48, 16)
    dim3 gA(SS, NHH, BB);

    for (int l = 0; l < NLL; l++) {
        const float* wq = qkv_w + ((size_t)l * 3 + 0) * HH * HH;
        const float* wk = qkv_w + ((size_t)l * 3 + 1) * HH * HH;
        const float* wv = qkv_w + ((size_t)l * 3 + 2) * HH * HH;
        const float* bq = qkv_b + ((size_t)l * 3 + 0) * HH;
        const float* bk = qkv_b + ((size_t)l * 3 + 1) * HH;
        const float* bv = qkv_b + ((size_t)l * 3 + 2) * HH;

        sgemm_bias<<<gH, 256>>>(ph, wq, bq, pq, TOK, HH, HH, 0);
        sgemm_bias<<<gH, 256>>>(ph, wk, bk, pk, TOK, HH, HH, 0);
        sgemm_bias<<<gH, 256>>>(ph, wv, bv, pv, TOK, HH, HH, 0);

        attn_kernel<<<gA, 256>>>();

        sgemm_bias<<<gH, 256>>>(pctx, attn_out_w + (size_t)l * HH * HH,
                                attn_out_b + (size_t)l * HH, pt1, TOK, HH, HH, 0);
        resid_ln_kernel<<<TOK, 256>>>(pt1, attn_ln_w + (size_t)l * HH,
                                      attn_ln_b + (size_t)l * HH);

        sgemm_bias<<<gF, 256>>>(ph, ffn_w1 + (size_t)l * HH * FFF,
                                ffn_b1 + (size_t)l * FFF, pffn, TOK, FFF, HH, 1);
        sgemm_bias<<<gH, 256>>>(pffn, ffn_w2 + (size_t)l * FFF * HH,
                                ffn_b2 + (size_t)l * HH, pt1, TOK, HH, FFF, 0);
        resid_ln_kernel<<<TOK, 256>>>(pt1, ffn_ln_w + (size_t)l * HH,
                                      ffn_ln_b + (size_t)l * HH);
    }

    emissions_kernel<<<TOK, 256>>>(cls_w, cls_b);
    crf_kernel<<<1, 128>>>(target, crf_start, crf_end, crf_trans, out);
}

// round 3
// speedup vs baseline: 2.5219x; 2.5219x over previous
#include <cuda_runtime.h>
#include <math.h>

#define BB   8
#define SS   256
#define HH   768
#define NLL  12
#define NHH  12
#define FFF  3072
#define CC   9
#define DHH  64
#define TOK  (BB*SS)   // 2048

// -------- scratch --------
__device__ float g_h  [TOK*HH];
__device__ float g_q  [TOK*HH];
__device__ float g_k  [TOK*HH];
__device__ float g_v  [TOK*HH];
__device__ float g_ctx[TOK*HH];
__device__ float g_t1 [TOK*HH];
__device__ float g_t2 [TOK*HH];
__device__ float g_ffn[TOK*FFF];
__device__ float g_em [TOK*CC];

// =================== embed + LN ===================
__global__ void embed_ln_kernel(const int* __restrict__ x,
                                const float* __restrict__ we,
                                const float* __restrict__ pe,
                                const float* __restrict__ te,
                                const float* __restrict__ lw,
                                const float* __restrict__ lb) {
    int t = blockIdx.x;
    int s = t % SS;
    int tid = threadIdx.x;
    int wid = x[t];

    float vals[3];
    float sum = 0.f, sq = 0.f;
#pragma unroll
    for (int r = 0; r < 3; r++) {
        int i = tid + r * 256;
        float v = we[(size_t)wid * HH + i] + pe[s * HH + i] + te[i];
        vals[r] = v; sum += v; sq += v * v;
    }
    __shared__ float red[256], red2[256];
    red[tid] = sum; red2[tid] = sq; __syncthreads();
    for (int off = 128; off > 0; off >>= 1) {
        if (tid < off) { red[tid] += red[tid + off]; red2[tid] += red2[tid + off]; }
        __syncthreads();
    }
    float m    = red[0] * (1.f / HH);
    float var  = red2[0] * (1.f / HH) - m * m;
    float rstd = rsqrtf(var + 1e-12f);
#pragma unroll
    for (int r = 0; r < 3; r++) {
        int i = tid + r * 256;
        g_h[(size_t)t * HH + i] = (vals[r] - m) * rstd * lw[i] + lb[i];
    }
}

// =================== residual add (two partials) + LN ===================
__global__ void resid_ln2_kernel(const float* __restrict__ a1,
                                 const float* __restrict__ a2,
                                 const float* __restrict__ lw,
                                 const float* __restrict__ lb) {
    int t = blockIdx.x;
    int tid = threadIdx.x;
    float vals[3];
    float sum = 0.f, sq = 0.f;
#pragma unroll
    for (int r = 0; r < 3; r++) {
        int i = tid + r * 256;
        size_t idx = (size_t)t * HH + i;
        float v = g_h[idx] + a1[idx] + a2[idx];
        vals[r] = v; sum += v; sq += v * v;
    }
    __shared__ float red[256], red2[256];
    red[tid] = sum; red2[tid] = sq; __syncthreads();
    for (int off = 128; off > 0; off >>= 1) {
        if (tid < off) { red[tid] += red[tid + off]; red2[tid] += red2[tid + off]; }
        __syncthreads();
    }
    float m    = red[0] * (1.f / HH);
    float var  = red2[0] * (1.f / HH) - m * m;
    float rstd = rsqrtf(var + 1e-12f);
#pragma unroll
    for (int r = 0; r < 3; r++) {
        int i = tid + r * 256;
        g_h[(size_t)t * HH + i] = (vals[r] - m) * rstd * lw[i] + lb[i];
    }
}

// =================== SGEMM core: 128x128 tile, BK=8, double buffered ===================
#define BM 128
#define BN 128
#define BKK 8

__device__ __forceinline__ float gelu_tanh(float v) {
    float c = 0.7978845608028654f * (v + 0.044715f * v * v * v);
    return 0.5f * v * (1.f + tanhf(c));
}

__device__ __forceinline__ void gemm_body(
    const float* __restrict__ A, int lda,
    const float* __restrict__ W, int ldw,
    const float* __restrict__ bias,
    float* __restrict__ C, int ldc,
    int K, int act, int rowBase, int colBase)
{
    __shared__ float As[2][BKK][BM];
    __shared__ float Bs[2][BKK][BN];

    int tid = threadIdx.x;
    int arow = tid >> 1, acol = (tid & 1) * 4;
    int brow = tid >> 5, bcol = (tid & 31) * 4;
    int ty = tid >> 4, tx = tid & 15;

    const float* Aptr = A + (size_t)(rowBase + arow) * lda + acol;
    const float* Wptr = W + (size_t)brow * ldw + colBase + bcol;

    // prefetch tile 0
    float4 av = *(const float4*)Aptr;
    float4 bv = *(const float4*)Wptr;
    As[0][acol + 0][arow] = av.x;
    As[0][acol + 1][arow] = av.y;
    As[0][acol + 2][arow] = av.z;
    As[0][acol + 3][arow] = av.w;
    *(float4*)&Bs[0][brow][bcol] = bv;
    __syncthreads();

    float acc[8][8];
#pragma unroll
    for (int i = 0; i < 8; i++)
#pragma unroll
        for (int j = 0; j < 8; j++) acc[i][j] = 0.f;

    int buf = 0;
    for (int k0 = BKK; k0 <= K; k0 += BKK) {
        float4 av2, bv2;
        bool more = (k0 < K);
        if (more) {
            av2 = *(const float4*)(Aptr + k0);
            bv2 = *(const float4*)(Wptr + (size_t)k0 * ldw);
        }
#pragma unroll
        for (int kk = 0; kk < BKK; kk++) {
            float a[8], b[8];
            float4 t;
            t = *(const float4*)&As[buf][kk][ty * 8];     a[0]=t.x; a[1]=t.y; a[2]=t.z; a[3]=t.w;
            t = *(const float4*)&As[buf][kk][ty * 8 + 4]; a[4]=t.x; a[5]=t.y; a[6]=t.z; a[7]=t.w;
            t = *(const float4*)&Bs[buf][kk][tx * 8];     b[0]=t.x; b[1]=t.y; b[2]=t.z; b[3]=t.w;
            t = *(const float4*)&Bs[buf][kk][tx * 8 + 4]; b[4]=t.x; b[5]=t.y; b[6]=t.z; b[7]=t.w;
#pragma unroll
            for (int i = 0; i < 8; i++)
#pragma unroll
                for (int j = 0; j < 8; j++)
                    acc[i][j] += a[i] * b[j];
        }
        if (more) {
            buf ^= 1;
            As[buf][acol + 0][arow] = av2.x;
            As[buf][acol + 1][arow] = av2.y;
            As[buf][acol + 2][arow] = av2.z;
            As[buf][acol + 3][arow] = av2.w;
            *(float4*)&Bs[buf][brow][bcol] = bv2;
            __syncthreads();
        }
    }

    // epilogue
    float bb[8];
#pragma unroll
    for (int j = 0; j < 8; j++)
        bb[j] = bias ? bias[colBase + tx * 8 + j] : 0.f;

#pragma unroll
    for (int i = 0; i < 8; i++) {
        size_t row = rowBase + ty * 8 + i;
        float out[8];
#pragma unroll
        for (int j = 0; j < 8; j++) {
            float v = acc[i][j] + bb[j];
            if (act) v = gelu_tanh(v);
            out[j] = v;
        }
        float* crow = C + row * (size_t)ldc + colBase + tx * 8;
        *(float4*)crow       = make_float4(out[0], out[1], out[2], out[3]);
        *(float4*)(crow + 4) = make_float4(out[4], out[5], out[6], out[7]);
    }
}

// QKV: grid (N/BN, M/BM, 3)
__global__ __launch_bounds__(256, 2)
void k_gemm_qkv(const float* __restrict__ A,
                const float* __restrict__ Wb,
                const float* __restrict__ Bb) {
    int z = blockIdx.z;
    const float* W = Wb + (size_t)z * HH * HH;
    const float* bias = Bb + (size_t)z * HH;
    float* C = (z == 0) ? g_q : (z == 1 ? g_k : g_v);
    gemm_body(A, HH, W, HH, bias, C, HH, HH, 0,
              blockIdx.y * BM, blockIdx.x * BN);
}

// plain (used for ffn1 with gelu)
__global__ __launch_bounds__(256, 2)
void k_gemm(const float* __restrict__ A,
            const float* __restrict__ W,
            const float* __restrict__ bias,
            float* __restrict__ C, int N, int K, int act) {
    gemm_body(A, K, W, N, bias, C, N, K, act,
              blockIdx.y * BM, blockIdx.x * BN);
}

// split-K=2: z selects half of K; z==0 -> g_t1 (+bias), z==1 -> g_t2
__global__ __launch_bounds__(256, 2)
void k_gemm_splitk2(const float* __restrict__ A,
                    const float* __restrict__ W,
                    const float* __restrict__ bias,
                    int N, int K) {
    int z = blockIdx.z;
    int Kh = K >> 1;
    const float* Az = A + (size_t)z * Kh;
    const float* Wz = W + (size_t)z * Kh * N;
    float* C = z ? g_t2 : g_t1;
    gemm_body(Az, K, Wz, N, z ? (const float*)0 : bias, C, N, Kh, 0,
              blockIdx.y * BM, blockIdx.x * BN);
}

// =================== attention v2: one CTA per (b,h) ===================
// smem: Qs[256][64] | KT[64][256] | Vs[256][64] | Ps[8][4][256]
__global__ void attn_kernel_v2() {
    extern __shared__ float sm[];
    float* Qs = sm;                   // 16384 floats? no: 256*64
    float* KT = Qs + 256 * 64;
    float* Vs = KT + 64 * 256;
    float* Ps = Vs + 256 * 64;

    int h = blockIdx.x, b = blockIdx.y;
    int tid = threadIdx.x, lane = tid & 31, w = tid >> 5;
    size_t base = (size_t)(b * SS) * HH + h * DHH;

    for (int i = tid; i < 256 * 16; i += 256) {
        int r = i >> 4, c4 = (i & 15) * 4;
        size_t g = base + (size_t)r * HH + c4;
        float4 q4 = *(const float4*)&g_q[g];
        *(float4*)&Qs[r * 64 + c4] = q4;
        float4 v4 = *(const float4*)&g_v[g];
        *(float4*)&Vs[r * 64 + c4] = v4;
        float4 k4 = *(const float4*)&g_k[g];
        KT[(c4 + 0) * 256 + r] = k4.x;
        KT[(c4 + 1) * 256 + r] = k4.y;
        KT[(c4 + 2) * 256 + r] = k4.z;
        KT[(c4 + 3) * 256 + r] = k4.w;
    }
    __syncthreads();

    for (int pass = 0; pass < 8; pass++) {
        int q0 = (pass * 8 + w) * 4;

        float acc[4][8];
#pragma unroll
        for (int i = 0; i < 4; i++)
#pragma unroll
            for (int j = 0; j < 8; j++) acc[i][j] = 0.f;

#pragma unroll 4
        for (int d = 0; d < 64; d++) {
            float kd[8];
#pragma unroll
            for (int j = 0; j < 8; j++) kd[j] = KT[d * 256 + j * 32 + lane];
#pragma unroll
            for (int i = 0; i < 4; i++) {
                float qd = Qs[(q0 + i) * 64 + d];
#pragma unroll
                for (int j = 0; j < 8; j++) acc[i][j] += qd * kd[j];
            }
        }

#pragma unroll
        for (int i = 0; i < 4; i++) {
            float m = -1e30f;
#pragma unroll
            for (int j = 0; j < 8; j++) m = fmaxf(m, acc[i][j]);
#pragma unroll
            for (int off = 16; off > 0; off >>= 1)
                m = fmaxf(m, __shfl_xor_sync(0xffffffffu, m, off));
            float e[8], s = 0.f;
#pragma unroll
            for (int j = 0; j < 8; j++) {
                e[j] = __expf(0.125f * (acc[i][j] - m));
                s += e[j];
            }
#pragma unroll
            for (int off = 16; off > 0; off >>= 1)
                s += __shfl_xor_sync(0xffffffffu, s, off);
            float inv = 1.f / s;
#pragma unroll
            for (int j = 0; j < 8; j++)
                Ps[(w * 4 + i) * 256 + j * 32 + lane] = e[j] * inv;
        }
        __syncwarp();

        float c[4][2];
#pragma unroll
        for (int i = 0; i < 4; i++) { c[i][0] = 0.f; c[i][1] = 0.f; }

        for (int k = 0; k < 256; k += 2) {
            float2 v0 = *(const float2*)&Vs[k * 64 + 2 * lane];
            float2 v1 = *(const float2*)&Vs[(k + 1) * 64 + 2 * lane];
#pragma unroll
            for (int i = 0; i < 4; i++) {
                float2 pk = *(const float2*)&Ps[(w * 4 + i) * 256 + k];
                c[i][0] += pk.x * v0.x + pk.y * v1.x;
                c[i][1] += pk.x * v0.y + pk.y * v1.y;
            }
        }
#pragma unroll
        for (int i = 0; i < 4; i++) {
            float2* dst = (float2*)&g_ctx[base + (size_t)(q0 + i) * HH + 2 * lane];
            *dst = make_float2(c[i][0], c[i][1]);
        }
        __syncthreads();
    }
}

// =================== emissions ===================
__global__ void emissions_kernel(const float* __restrict__ cw,
                                 const float* __restrict__ cb) {
    int t = blockIdx.x;
    int tid = threadIdx.x;
    float part[CC];
#pragma unroll
    for (int c = 0; c < CC; c++) part[c] = 0.f;
    for (int k = tid; k < HH; k += 256) {
        float hv = g_h[(size_t)t * HH + k];
        const float* wr = cw + (size_t)k * CC;
#pragma unroll
        for (int c = 0; c < CC; c++) part[c] += hv * wr[c];
    }
#pragma unroll
    for (int c = 0; c < CC; c++)
        for (int off = 16; off > 0; off >>= 1)
            part[c] += __shfl_down_sync(0xffffffffu, part[c], off);

    __shared__ float wred[8][CC];
    int lane = tid & 31, w = tid >> 5;
    if (lane == 0)
#pragma unroll
        for (int c = 0; c < CC; c++) wred[w][c] = part[c];
    __syncthreads();
    if (tid < CC) {
        float s = cb[tid];
#pragma unroll
        for (int ww = 0; ww < 8; ww++) s += wred[ww][tid];
        g_em[(size_t)t * CC + tid] = s;
    }
}

// =================== CRF ===================
__global__ void crf_kernel(const int* __restrict__ target,
                           const float* __restrict__ cstart,
                           const float* __restrict__ cend,
                           const float* __restrict__ ctrans,
                           float* __restrict__ out) {
    __shared__ float alpha[BB][CC];
    __shared__ float trans[CC][CC];
    __shared__ float den[BB], num[BB];
    int tid = threadIdx.x;

    if (tid < CC * CC) trans[tid / CC][tid % CC] = ctrans[tid];
    __syncthreads();

    int b = tid / CC, j = tid % CC;
    bool act = (tid < BB * CC);
    if (act) alpha[b][j] = cstart[j] + g_em[(size_t)(b * SS) * CC + j];
    __syncthreads();

    for (int s = 1; s < SS; s++) {
        float nv = 0.f;
        if (act) {
            float m = -1e30f;
#pragma unroll
            for (int i = 0; i < CC; i++) m = fmaxf(m, alpha[b][i] + trans[i][j]);
            float sum = 0.f;
#pragma unroll
            for (int i = 0; i < CC; i++) sum += __expf(alpha[b][i] + trans[i][j] - m);
            nv = m + __logf(sum) + g_em[(size_t)(b * SS + s) * CC + j];
            if (!(target[b * SS + s] > -1)) nv = alpha[b][j];
        }
        __syncthreads();
        if (act) alpha[b][j] = nv;
        __syncthreads();
    }

    if (act && j == 0) {
        float m = -1e30f;
#pragma unroll
        for (int jj = 0; jj < CC; jj++) m = fmaxf(m, alpha[b][jj] + cend[jj]);
        float sum = 0.f;
#pragma unroll
        for (int jj = 0; jj < CC; jj++) sum += __expf(alpha[b][jj] + cend[jj] - m);
        den[b] = m + __logf(sum);

        const int* tb = target + b * SS;
        int cnt = 0;
        for (int s = 0; s < SS; s++) cnt += (tb[s] > -1) ? 1 : 0;
        int send = cnt - 1;
        int t0 = tb[0] < 0 ? 0 : tb[0];
        float nu = cstart[t0] + g_em[(size_t)(b * SS) * CC + t0];
        for (int s = 1; s < SS; s++) {
            int ts = tb[s], tp = tb[s - 1];
            float mk = (ts > -1) ? 1.f : 0.f;
            int tsc = ts < 0 ? 0 : ts, tpc = tp < 0 ? 0 : tp;
            nu += mk * (trans[tpc][tsc] + g_em[(size_t)(b * SS + s) * CC + tsc]);
        }
        int last = tb[send < 0 ? 0 : send];
        nu += cend[last < 0 ? 0 : last];
        num[b] = nu;
    }
    __syncthreads();
    if (tid == 0) {
        float L = 0.f;
        for (int bb = 0; bb < BB; bb++) L += num[bb] - den[bb];
        out[0] = -L / BB;
    }
}

// =================== launch ===================
extern "C" void kernel_launch(void* const* d_in, const int* in_sizes, int n_in,
                              void* d_out, int out_size) {
    const int*   x          = (const int*)  d_in[0];
    const int*   target     = (const int*)  d_in[1];
    const float* word_emb   = (const float*)d_in[2];
    const float* pos_emb    = (const float*)d_in[3];
    const float* type_emb   = (const float*)d_in[4];
    const float* emb_ln_w   = (const float*)d_in[5];
    const float* emb_ln_b   = (const float*)d_in[6];
    const float* qkv_w      = (const float*)d_in[7];
    const float* qkv_b      = (const float*)d_in[8];
    const float* attn_out_w = (const float*)d_in[9];
    const float* attn_out_b = (const float*)d_in[10];
    const float* attn_ln_w  = (const float*)d_in[11];
    const float* attn_ln_b  = (const float*)d_in[12];
    const float* ffn_w1     = (const float*)d_in[13];
    const float* ffn_b1     = (const float*)d_in[14];
    const float* ffn_w2     = (const float*)d_in[15];
    const float* ffn_b2     = (const float*)d_in[16];
    const float* ffn_ln_w   = (const float*)d_in[17];
    const float* ffn_ln_b   = (const float*)d_in[18];
    const float* cls_w      = (const float*)d_in[19];
    const float* cls_b      = (const float*)d_in[20];
    const float* crf_start  = (const float*)d_in[21];
    const float* crf_end    = (const float*)d_in[22];
    const float* crf_trans  = (const float*)d_in[23];
    float* out = (float*)d_out;

    // IMPORTANT: __device__ symbols must be resolved to device addresses.
    float *ph, *pctx, *pffn, *pt1, *pt2;
    cudaGetSymbolAddress((void**)&ph,   g_h);
    cudaGetSymbolAddress((void**)&pctx, g_ctx);
    cudaGetSymbolAddress((void**)&pffn, g_ffn);
    cudaGetSymbolAddress((void**)&pt1,  g_t1);
    cudaGetSymbolAddress((void**)&pt2,  g_t2);

    const int SMEM_ATTN = (256 * 64 + 64 * 256 + 256 * 64 + 8 * 4 * 256) * 4; // 229376
    cudaFuncSetAttribute(attn_kernel_v2,
                         cudaFuncAttributeMaxDynamicSharedMemorySize, SMEM_ATTN);

    embed_ln_kernel<<<TOK, 256>>>(x, word_emb, pos_emb, type_emb, emb_ln_w, emb_ln_b);

    dim3 gQKV(HH / BN, TOK / BM, 3);    // (6,16,3)
    dim3 gH2 (HH / BN, TOK / BM, 2);    // (6,16,2)
    dim3 gF  (FFF / BN, TOK / BM);      // (24,16)
    dim3 gA  (NHH, BB);                 // 96

    for (int l = 0; l < NLL; l++) {
        k_gemm_qkv<<<gQKV, 256>>>(ph,
                                  qkv_w + (size_t)l * 3 * HH * HH,
                                  qkv_b + (size_t)l * 3 * HH);

        attn_kernel_v2<<<gA, 256, SMEM_ATTN>>>();

        k_gemm_splitk2<<<gH2, 256>>>(pctx,
                                     attn_out_w + (size_t)l * HH * HH,
                                     attn_out_b + (size_t)l * HH, HH, HH);
        resid_ln2_kernel<<<TOK, 256>>>(pt1, pt2,
                                       attn_ln_w + (size_t)l * HH,
                                       attn_ln_b + (size_t)l * HH);

        k_gemm<<<gF, 256>>>(ph, ffn_w1 + (size_t)l * HH * FFF,
                            ffn_b1 + (size_t)l * FFF, pffn, FFF, HH, 1);
        k_gemm_splitk2<<<gH2, 256>>>(pffn,
                                     ffn_w2 + (size_t)l * FFF * HH,
                                     ffn_b2 + (size_t)l * HH, HH, FFF);
        resid_ln2_kernel<<<TOK, 256>>>(pt1, pt2,
                                       ffn_ln_w + (size_t)l * HH,
                                       ffn_ln_b + (size_t)l * HH);
    }

    emissions_kernel<<<TOK, 256>>>(cls_w, cls_b);
    crf_kernel<<<1, 128>>>(target, crf_start, crf_end, crf_trans, out);
}

// round 5
// speedup vs baseline: 5.0171x; 1.9894x over previous
#include <cuda_runtime.h>
#include <cuda_bf16.h>
#include <math.h>
#include <stdint.h>

#define BB   8
#define SS   256
#define HH   768
#define NLL  12
#define NHH  12
#define FFF  3072
#define CC   9
#define DHH  64
#define TOK  (BB*SS)   // 2048

// ================= scratch (static device globals) =================
__device__ float                         g_h   [TOK*HH];
__device__ __align__(256) __nv_bfloat16  g_h_hi[TOK*HH];
__device__ __align__(256) __nv_bfloat16  g_h_lo[TOK*HH];
__device__ float                         g_qkv [3*TOK*HH];
__device__ __align__(256) __nv_bfloat16  g_cx_hi[TOK*HH];
__device__ __align__(256) __nv_bfloat16  g_cx_lo[TOK*HH];
__device__ float                         g_t1  [TOK*HH];
__device__ __align__(256) __nv_bfloat16  g_f_hi[TOK*FFF];
__device__ __align__(256) __nv_bfloat16  g_f_lo[TOK*FFF];
__device__ float                         g_em  [TOK*CC];

// transposed+split weights  Wt[N][K]
__device__ __align__(256) __nv_bfloat16 w_qkv_hi[NLL*3*HH*HH];
__device__ __align__(256) __nv_bfloat16 w_qkv_lo[NLL*3*HH*HH];
__device__ __align__(256) __nv_bfloat16 w_ao_hi [NLL*HH*HH];
__device__ __align__(256) __nv_bfloat16 w_ao_lo [NLL*HH*HH];
__device__ __align__(256) __nv_bfloat16 w_f1_hi [NLL*HH*FFF];
__device__ __align__(256) __nv_bfloat16 w_f1_lo [NLL*HH*FFF];
__device__ __align__(256) __nv_bfloat16 w_f2_hi [NLL*FFF*HH];
__device__ __align__(256) __nv_bfloat16 w_f2_lo [NLL*FFF*HH];

// ================= low-level helpers (baseline sm_80+ PTX only) =================
__device__ __forceinline__ void cpa16(uint32_t dst, const void* src) {
    asm volatile("cp.async.cg.shared.global [%0], [%1], 16;"
                 :: "r"(dst), "l"(src) : "memory");
}
#define CP_COMMIT() asm volatile("cp.async.commit_group;" ::: "memory")
#define CP_WAIT1()  asm volatile("cp.async.wait_group 1;" ::: "memory")
#define CP_WAIT0()  asm volatile("cp.async.wait_group 0;" ::: "memory")

__device__ __forceinline__ void ldm_x4(uint32_t* r, uint32_t a) {
    asm volatile("ldmatrix.sync.aligned.m8n8.x4.shared.b16 {%0,%1,%2,%3}, [%4];"
                 : "=r"(r[0]), "=r"(r[1]), "=r"(r[2]), "=r"(r[3]) : "r"(a));
}
__device__ __forceinline__ void mma16816(float* c, const uint32_t* a, const uint32_t* b) {
    asm volatile("mma.sync.aligned.m16n8k16.row.col.f32.bf16.bf16.f32 "
        "{%0,%1,%2,%3}, {%4,%5,%6,%7}, {%8,%9}, {%0,%1,%2,%3};"
        : "+f"(c[0]), "+f"(c[1]), "+f"(c[2]), "+f"(c[3])
        : "r"(a[0]), "r"(a[1]), "r"(a[2]), "r"(a[3]), "r"(b[0]), "r"(b[1]));
}

__device__ __forceinline__ float gelu_tanh(float v) {
    float c = 0.7978845608028654f * (v + 0.044715f * v * v * v);
    return 0.5f * v * (1.f + tanhf(c));
}
__device__ __forceinline__ void split_bf16(float v, __nv_bfloat16& h, __nv_bfloat16& l) {
    h = __float2bfloat16(v);
    l = __float2bfloat16(v - __bfloat162float(h));
}

// ================= weight transpose + split =================
__global__ void k_wsplit(const float* __restrict__ W,
                         __nv_bfloat16* __restrict__ hi,
                         __nv_bfloat16* __restrict__ lo,
                         int K, int N) {
    __shared__ float t[32][33];
    size_t moff = (size_t)blockIdx.z * K * N;
    int n0 = blockIdx.x * 32, k0 = blockIdx.y * 32;
    for (int dy = threadIdx.y; dy < 32; dy += 8)
        t[dy][threadIdx.x] = W[moff + (size_t)(k0 + dy) * N + n0 + threadIdx.x];
    __syncthreads();
    for (int dy = threadIdx.y; dy < 32; dy += 8) {
        float v = t[threadIdx.x][dy];
        size_t o = moff + (size_t)(n0 + dy) * K + k0 + threadIdx.x;
        __nv_bfloat16 h, l; split_bf16(v, h, l);
        hi[o] = h; lo[o] = l;
    }
}

// ================= HMMA GEMM: C[M,N] = A[M,K] @ Wt[N,K]^T =================
// 3xbf16 split: D = Ahi*Bhi + Ahi*Blo + Alo*Bhi, fp32 accum.
// CTA tile 128 x BN, BK=32, cp.async double buffered, 8 warps.
#define PADK 40   // 32 + 8 halves padding -> conflict-free ldmatrix

template<int BN>
__global__ __launch_bounds__(256, 1)
void k_mma(const __nv_bfloat16* __restrict__ A_hi,
           const __nv_bfloat16* __restrict__ A_lo,
           const __nv_bfloat16* __restrict__ B_hi,
           const __nv_bfloat16* __restrict__ B_lo,
           const float* __restrict__ bias,
           float* __restrict__ Cf,
           __nv_bfloat16* __restrict__ Chi,
           __nv_bfloat16* __restrict__ Clo,
           int N, int K, int mode,
           int zW, int zC, int zB)
{
    constexpr int WMW = (BN == 128) ? 2 : 4;   // warps along M
    constexpr int WTM = 128 / WMW;             // 64 or 32
    constexpr int WTN = BN * WMW / 8;          // 32
    constexpr int MT  = WTM / 16;              // 4 or 2
    constexpr int ASZ = 128 * PADK;            // halves
    constexpr int BSZ = BN  * PADK;
    constexpr int STG = 2 * ASZ + 2 * BSZ;     // halves per stage

    extern __shared__ __nv_bfloat16 smem_dyn[];
    uint32_t smb = (uint32_t)__cvta_generic_to_shared(smem_dyn);

    int tid = threadIdx.x, wid = tid >> 5, lane = tid & 31;
    int n0 = blockIdx.x * BN, m0 = blockIdx.y * 128, z = blockIdx.z;
    B_hi += (size_t)z * zW;  B_lo += (size_t)z * zW;
    bias += (size_t)z * zB;
    if (Cf) Cf += (size_t)z * zC;

    int wm = (wid % WMW) * WTM;
    int wn = (wid / WMW) * WTN;

    float acc[MT][4][4];
#pragma unroll
    for (int mt = 0; mt < MT; mt++)
#pragma unroll
        for (int nt = 0; nt < 4; nt++)
#pragma unroll
            for (int f = 0; f < 4; f++) acc[mt][nt][f] = 0.f;

    auto load_stage = [&](int s, int k0) {
        uint32_t base = smb + (uint32_t)(s * STG) * 2;
        // A hi/lo: 128 rows x 4 chunks of 16B
#pragma unroll
        for (int i = 0; i < 2; i++) {
            int idx = tid + i * 256;
            int r = idx >> 2, ch = idx & 3;
            const char* g0 = (const char*)(A_hi + (size_t)(m0 + r) * K + k0) + ch * 16;
            const char* g1 = (const char*)(A_lo + (size_t)(m0 + r) * K + k0) + ch * 16;
            cpa16(base + (uint32_t)(r * PADK) * 2 + ch * 16, g0);
            cpa16(base + (uint32_t)(ASZ + r * PADK) * 2 + ch * 16, g1);
        }
        // B hi/lo: BN rows x 4 chunks
#pragma unroll
        for (int i = 0; i < (BN * 4) / 256; i++) {
            int idx = tid + i * 256;
            int r = idx >> 2, ch = idx & 3;
            const char* g0 = (const char*)(B_hi + (size_t)(n0 + r) * K + k0) + ch * 16;
            const char* g1 = (const char*)(B_lo + (size_t)(n0 + r) * K + k0) + ch * 16;
            cpa16(base + (uint32_t)(2 * ASZ + r * PADK) * 2 + ch * 16, g0);
            cpa16(base + (uint32_t)(2 * ASZ + BSZ + r * PADK) * 2 + ch * 16, g1);
        }
    };

    int nc = K / 32;
    load_stage(0, 0);
    CP_COMMIT();

    // per-lane ldmatrix index components
    uint32_t aRow = (uint32_t)(wm + (lane & 15));
    uint32_t aK   = (uint32_t)((lane >> 4) * 8);
    uint32_t bRow = (uint32_t)(wn + ((lane >> 4) & 1) * 8 + (lane & 7));
    uint32_t bK   = (uint32_t)(((lane >> 3) & 1) * 8);

    for (int c = 0; c < nc; c++) {
        int b = c & 1;
        if (c + 1 < nc) {
            load_stage(b ^ 1, (c + 1) * 32);
            CP_COMMIT();
            CP_WAIT1();
        } else {
            CP_WAIT0();
        }
        __syncthreads();

        uint32_t sbase = smb + (uint32_t)(b * STG) * 2;
#pragma unroll
        for (int k16 = 0; k16 < 2; k16++) {
            uint32_t ah[MT][4], al[MT][4];
#pragma unroll
            for (int mt = 0; mt < MT; mt++) {
                uint32_t off = ((aRow + mt * 16) * PADK + (uint32_t)(k16 * 16) + aK) * 2;
                ldm_x4(ah[mt], sbase + off);
                ldm_x4(al[mt], sbase + (uint32_t)ASZ * 2 + off);
            }
            uint32_t bh[2][4], bl[2][4];
#pragma unroll
            for (int np = 0; np < 2; np++) {
                uint32_t off = ((bRow + np * 16) * PADK + (uint32_t)(k16 * 16) + bK) * 2;
                ldm_x4(bh[np], sbase + (uint32_t)(2 * ASZ) * 2 + off);
                ldm_x4(bl[np], sbase + (uint32_t)(2 * ASZ + BSZ) * 2 + off);
            }
#pragma unroll
            for (int mt = 0; mt < MT; mt++)
#pragma unroll
                for (int nt = 0; nt < 4; nt++) {
                    const uint32_t* Bh = &bh[nt >> 1][(nt & 1) * 2];
                    const uint32_t* Bl = &bl[nt >> 1][(nt & 1) * 2];
                    mma16816(acc[mt][nt], ah[mt], Bh);
                    mma16816(acc[mt][nt], ah[mt], Bl);
                    mma16816(acc[mt][nt], al[mt], Bh);
                }
        }
        __syncthreads();
    }

    // epilogue: c frag -> rows (lane/4, lane/4+8), cols (lane%4)*2
    int rbase = m0 + wm + (lane >> 2);
#pragma unroll
    for (int mt = 0; mt < MT; mt++) {
        int row = rbase + mt * 16;
#pragma unroll
        for (int nt = 0; nt < 4; nt++) {
            int col = n0 + wn + nt * 8 + (lane & 3) * 2;
            float b0 = bias[col], b1 = bias[col + 1];
            float v0 = acc[mt][nt][0] + b0;
            float v1 = acc[mt][nt][1] + b1;
            float v2 = acc[mt][nt][2] + b0;
            float v3 = acc[mt][nt][3] + b1;
            if (mode == 0) {
                *(float2*)(Cf + (size_t)row * N + col)       = make_float2(v0, v1);
                *(float2*)(Cf + (size_t)(row + 8) * N + col) = make_float2(v2, v3);
            } else {
                v0 = gelu_tanh(v0); v1 = gelu_tanh(v1);
                v2 = gelu_tanh(v2); v3 = gelu_tanh(v3);
                __nv_bfloat16 h0, l0, h1, l1;
                split_bf16(v0, h0, l0); split_bf16(v1, h1, l1);
                *(__nv_bfloat162*)(Chi + (size_t)row * N + col) = __halves2bfloat162(h0, h1);
                *(__nv_bfloat162*)(Clo + (size_t)row * N + col) = __halves2bfloat162(l0, l1);
                split_bf16(v2, h0, l0); split_bf16(v3, h1, l1);
                *(__nv_bfloat162*)(Chi + (size_t)(row + 8) * N + col) = __halves2bfloat162(h0, h1);
                *(__nv_bfloat162*)(Clo + (size_t)(row + 8) * N + col) = __halves2bfloat162(l0, l1);
            }
        }
    }
}

// ================= embed + LN (writes h, h_hi, h_lo) =================
__global__ void embed_ln_kernel(const int* __restrict__ x,
                                const float* __restrict__ we,
                                const float* __restrict__ pe,
                                const float* __restrict__ te,
                                const float* __restrict__ lw,
                                const float* __restrict__ lb) {
    int t = blockIdx.x, s = t % SS, tid = threadIdx.x;
    int wid = x[t];
    float vals[3]; float sum = 0.f, sq = 0.f;
#pragma unroll
    for (int r = 0; r < 3; r++) {
        int i = tid + r * 256;
        float v = we[(size_t)wid * HH + i] + pe[s * HH + i] + te[i];
        vals[r] = v; sum += v; sq += v * v;
    }
    __shared__ float red[256], red2[256];
    red[tid] = sum; red2[tid] = sq; __syncthreads();
    for (int off = 128; off > 0; off >>= 1) {
        if (tid < off) { red[tid] += red[tid+off]; red2[tid] += red2[tid+off]; }
        __syncthreads();
    }
    float m = red[0] * (1.f/HH), var = red2[0] * (1.f/HH) - m*m;
    float rstd = rsqrtf(var + 1e-12f);
#pragma unroll
    for (int r = 0; r < 3; r++) {
        int i = tid + r * 256;
        float v = (vals[r] - m) * rstd * lw[i] + lb[i];
        size_t idx = (size_t)t * HH + i;
        g_h[idx] = v;
        __nv_bfloat16 h, l; split_bf16(v, h, l);
        g_h_hi[idx] = h; g_h_lo[idx] = l;
    }
}

// ================= residual + LN (writes h, h_hi, h_lo) =================
__global__ void resid_ln_kernel(const float* __restrict__ add,
                                const float* __restrict__ lw,
                                const float* __restrict__ lb) {
    int t = blockIdx.x, tid = threadIdx.x;
    float vals[3]; float sum = 0.f, sq = 0.f;
#pragma unroll
    for (int r = 0; r < 3; r++) {
        int i = tid + r * 256;
        size_t idx = (size_t)t * HH + i;
        float v = g_h[idx] + add[idx];
        vals[r] = v; sum += v; sq += v * v;
    }
    __shared__ float red[256], red2[256];
    red[tid] = sum; red2[tid] = sq; __syncthreads();
    for (int off = 128; off > 0; off >>= 1) {
        if (tid < off) { red[tid] += red[tid+off]; red2[tid] += red2[tid+off]; }
        __syncthreads();
    }
    float m = red[0] * (1.f/HH), var = red2[0] * (1.f/HH) - m*m;
    float rstd = rsqrtf(var + 1e-12f);
#pragma unroll
    for (int r = 0; r < 3; r++) {
        int i = tid + r * 256;
        float v = (vals[r] - m) * rstd * lw[i] + lb[i];
        size_t idx = (size_t)t * HH + i;
        g_h[idx] = v;
        __nv_bfloat16 h, l; split_bf16(v, h, l);
        g_h_hi[idx] = h; g_h_lo[idx] = l;
    }
}

// ================= attention (fp32, smem-resident), writes ctx hi/lo =================
__global__ void attn_kernel_v2() {
    extern __shared__ float sm[];
    float* Qs = sm;
    float* KT = Qs + 256 * 64;
    float* Vs = KT + 64 * 256;
    float* Ps = Vs + 256 * 64;

    const float* gq = g_qkv;
    const float* gk = g_qkv + (size_t)TOK * HH;
    const float* gv = g_qkv + 2 * (size_t)TOK * HH;

    int h = blockIdx.x, b = blockIdx.y;
    int tid = threadIdx.x, lane = tid & 31, w = tid >> 5;
    size_t base = (size_t)(b * SS) * HH + h * DHH;

    for (int i = tid; i < 256 * 16; i += 256) {
        int r = i >> 4, c4 = (i & 15) * 4;
        size_t g = base + (size_t)r * HH + c4;
        *(float4*)&Qs[r * 64 + c4] = *(const float4*)&gq[g];
        *(float4*)&Vs[r * 64 + c4] = *(const float4*)&gv[g];
        float4 k4 = *(const float4*)&gk[g];
        KT[(c4 + 0) * 256 + r] = k4.x;
        KT[(c4 + 1) * 256 + r] = k4.y;
        KT[(c4 + 2) * 256 + r] = k4.z;
        KT[(c4 + 3) * 256 + r] = k4.w;
    }
    __syncthreads();

    for (int pass = 0; pass < 8; pass++) {
        int q0 = (pass * 8 + w) * 4;
        float acc[4][8];
#pragma unroll
        for (int i = 0; i < 4; i++)
#pragma unroll
            for (int j = 0; j < 8; j++) acc[i][j] = 0.f;

#pragma unroll 4
        for (int d = 0; d < 64; d++) {
            float kd[8];
#pragma unroll
            for (int j = 0; j < 8; j++) kd[j] = KT[d * 256 + j * 32 + lane];
#pragma unroll
            for (int i = 0; i < 4; i++) {
                float qd = Qs[(q0 + i) * 64 + d];
#pragma unroll
                for (int j = 0; j < 8; j++) acc[i][j] += qd * kd[j];
            }
        }

#pragma unroll
        for (int i = 0; i < 4; i++) {
            float m = -1e30f;
#pragma unroll
            for (int j = 0; j < 8; j++) m = fmaxf(m, acc[i][j]);
#pragma unroll
            for (int off = 16; off > 0; off >>= 1)
                m = fmaxf(m, __shfl_xor_sync(0xffffffffu, m, off));
            float e[8], s = 0.f;
#pragma unroll
            for (int j = 0; j < 8; j++) {
                e[j] = __expf(0.125f * (acc[i][j] - m));
                s += e[j];
            }
#pragma unroll
            for (int off = 16; off > 0; off >>= 1)
                s += __shfl_xor_sync(0xffffffffu, s, off);
            float inv = 1.f / s;
#pragma unroll
            for (int j = 0; j < 8; j++)
                Ps[(w * 4 + i) * 256 + j * 32 + lane] = e[j] * inv;
        }
        __syncwarp();

        float c[4][2];
#pragma unroll
        for (int i = 0; i < 4; i++) { c[i][0] = 0.f; c[i][1] = 0.f; }
        for (int k = 0; k < 256; k += 2) {
            float2 v0 = *(const float2*)&Vs[k * 64 + 2 * lane];
            float2 v1 = *(const float2*)&Vs[(k + 1) * 64 + 2 * lane];
#pragma unroll
            for (int i = 0; i < 4; i++) {
                float2 pk = *(const float2*)&Ps[(w * 4 + i) * 256 + k];
                c[i][0] += pk.x * v0.x + pk.y * v1.x;
                c[i][1] += pk.x * v0.y + pk.y * v1.y;
            }
        }
#pragma unroll
        for (int i = 0; i < 4; i++) {
            size_t idx = base + (size_t)(q0 + i) * HH + 2 * lane;
            __nv_bfloat16 h0, l0, h1, l1;
            split_bf16(c[i][0], h0, l0);
            split_bf16(c[i][1], h1, l1);
            *(__nv_bfloat162*)(g_cx_hi + idx) = __halves2bfloat162(h0, h1);
            *(__nv_bfloat162*)(g_cx_lo + idx) = __halves2bfloat162(l0, l1);
        }
        __syncthreads();
    }
}

// ================= emissions =================
__global__ void emissions_kernel(const float* __restrict__ cw,
                                 const float* __restrict__ cb) {
    int t = blockIdx.x, tid = threadIdx.x;
    float part[CC];
#pragma unroll
    for (int c = 0; c < CC; c++) part[c] = 0.f;
    for (int k = tid; k < HH; k += 256) {
        float hv = g_h[(size_t)t * HH + k];
        const float* wr = cw + (size_t)k * CC;
#pragma unroll
        for (int c = 0; c < CC; c++) part[c] += hv * wr[c];
    }
#pragma unroll
    for (int c = 0; c < CC; c++)
        for (int off = 16; off > 0; off >>= 1)
            part[c] += __shfl_down_sync(0xffffffffu, part[c], off);

    __shared__ float wred[8][CC];
    int lane = tid & 31, w = tid >> 5;
    if (lane == 0)
#pragma unroll
        for (int c = 0; c < CC; c++) wred[w][c] = part[c];
    __syncthreads();
    if (tid < CC) {
        float s = cb[tid];
#pragma unroll
        for (int ww = 0; ww < 8; ww++) s += wred[ww][tid];
        g_em[(size_t)t * CC + tid] = s;
    }
}

// ================= CRF =================
__global__ void crf_kernel(const int* __restrict__ target,
                           const float* __restrict__ cstart,
                           const float* __restrict__ cend,
                           const float* __restrict__ ctrans,
                           float* __restrict__ out) {
    __shared__ float alpha[BB][CC];
    __shared__ float trans[CC][CC];
    __shared__ float den[BB], num[BB];
    int tid = threadIdx.x;

    if (tid < CC * CC) trans[tid / CC][tid % CC] = ctrans[tid];
    __syncthreads();

    int b = tid / CC, j = tid % CC;
    bool act = (tid < BB * CC);
    if (act) alpha[b][j] = cstart[j] + g_em[(size_t)(b * SS) * CC + j];
    __syncthreads();

    for (int s = 1; s < SS; s++) {
        float nv = 0.f;
        if (act) {
            float m = -1e30f;
#pragma unroll
            for (int i = 0; i < CC; i++) m = fmaxf(m, alpha[b][i] + trans[i][j]);
            float sum = 0.f;
#pragma unroll
            for (int i = 0; i < CC; i++) sum += __expf(alpha[b][i] + trans[i][j] - m);
            nv = m + __logf(sum) + g_em[(size_t)(b * SS + s) * CC + j];
            if (!(target[b * SS + s] > -1)) nv = alpha[b][j];
        }
        __syncthreads();
        if (act) alpha[b][j] = nv;
        __syncthreads();
    }

    if (act && j == 0) {
        float m = -1e30f;
#pragma unroll
        for (int jj = 0; jj < CC; jj++) m = fmaxf(m, alpha[b][jj] + cend[jj]);
        float sum = 0.f;
#pragma unroll
        for (int jj = 0; jj < CC; jj++) sum += __expf(alpha[b][jj] + cend[jj] - m);
        den[b] = m + __logf(sum);

        const int* tb = target + b * SS;
        int cnt = 0;
        for (int s = 0; s < SS; s++) cnt += (tb[s] > -1) ? 1 : 0;
        int send = cnt - 1;
        int t0 = tb[0] < 0 ? 0 : tb[0];
        float nu = cstart[t0] + g_em[(size_t)(b * SS) * CC + t0];
        for (int s = 1; s < SS; s++) {
            int ts = tb[s], tp = tb[s - 1];
            float mk = (ts > -1) ? 1.f : 0.f;
            int tsc = ts < 0 ? 0 : ts, tpc = tp < 0 ? 0 : tp;
            nu += mk * (trans[tpc][tsc] + g_em[(size_t)(b * SS + s) * CC + tsc]);
        }
        int last = tb[send < 0 ? 0 : send];
        nu += cend[last < 0 ? 0 : last];
        num[b] = nu;
    }
    __syncthreads();
    if (tid == 0) {
        float L = 0.f;
        for (int bb = 0; bb < BB; bb++) L += num[bb] - den[bb];
        out[0] = -L / BB;
    }
}

// ================= launch =================
extern "C" void kernel_launch(void* const* d_in, const int* in_sizes, int n_in,
                              void* d_out, int out_size) {
    const int*   x          = (const int*)  d_in[0];
    const int*   target     = (const int*)  d_in[1];
    const float* word_emb   = (const float*)d_in[2];
    const float* pos_emb    = (const float*)d_in[3];
    const float* type_emb   = (const float*)d_in[4];
    const float* emb_ln_w   = (const float*)d_in[5];
    const float* emb_ln_b   = (const float*)d_in[6];
    const float* qkv_w      = (const float*)d_in[7];
    const float* qkv_b      = (const float*)d_in[8];
    const float* attn_out_w = (const float*)d_in[9];
    const float* attn_out_b = (const float*)d_in[10];
    const float* attn_ln_w  = (const float*)d_in[11];
    const float* attn_ln_b  = (const float*)d_in[12];
    const float* ffn_w1     = (const float*)d_in[13];
    const float* ffn_b1     = (const float*)d_in[14];
    const float* ffn_w2     = (const float*)d_in[15];
    const float* ffn_b2     = (const float*)d_in[16];
    const float* ffn_ln_w   = (const float*)d_in[17];
    const float* ffn_ln_b   = (const float*)d_in[18];
    const float* cls_w      = (const float*)d_in[19];
    const float* cls_b      = (const float*)d_in[20];
    const float* crf_start  = (const float*)d_in[21];
    const float* crf_end    = (const float*)d_in[22];
    const float* crf_trans  = (const float*)d_in[23];
    float* out = (float*)d_out;

    float *pt1, *pqkv;
    __nv_bfloat16 *ph_hi, *ph_lo, *pcx_hi, *pcx_lo, *pf_hi, *pf_lo;
    __nv_bfloat16 *pwq_hi, *pwq_lo, *pwa_hi, *pwa_lo, *pw1_hi, *pw1_lo, *pw2_hi, *pw2_lo;
    cudaGetSymbolAddress((void**)&pt1,    g_t1);
    cudaGetSymbolAddress((void**)&pqkv,   g_qkv);
    cudaGetSymbolAddress((void**)&ph_hi,  g_h_hi);
    cudaGetSymbolAddress((void**)&ph_lo,  g_h_lo);
    cudaGetSymbolAddress((void**)&pcx_hi, g_cx_hi);
    cudaGetSymbolAddress((void**)&pcx_lo, g_cx_lo);
    cudaGetSymbolAddress((void**)&pf_hi,  g_f_hi);
    cudaGetSymbolAddress((void**)&pf_lo,  g_f_lo);
    cudaGetSymbolAddress((void**)&pwq_hi, w_qkv_hi);
    cudaGetSymbolAddress((void**)&pwq_lo, w_qkv_lo);
    cudaGetSymbolAddress((void**)&pwa_hi, w_ao_hi);
    cudaGetSymbolAddress((void**)&pwa_lo, w_ao_lo);
    cudaGetSymbolAddress((void**)&pw1_hi, w_f1_hi);
    cudaGetSymbolAddress((void**)&pw1_lo, w_f1_lo);
    cudaGetSymbolAddress((void**)&pw2_hi, w_f2_hi);
    cudaGetSymbolAddress((void**)&pw2_lo, w_f2_lo);

    const int SMEM_ATTN = (256*64 + 64*256 + 256*64 + 8*4*256) * 4;
    const int SMEM_G128 = 2 * (2*128*PADK + 2*128*PADK) * 2;   // 81920
    const int SMEM_G64  = 2 * (2*128*PADK + 2*64*PADK) * 2;    // 61440
    cudaFuncSetAttribute(attn_kernel_v2,
                         cudaFuncAttributeMaxDynamicSharedMemorySize, SMEM_ATTN);
    cudaFuncSetAttribute(k_mma<128>,
                         cudaFuncAttributeMaxDynamicSharedMemorySize, SMEM_G128);
    cudaFuncSetAttribute(k_mma<64>,
                         cudaFuncAttributeMaxDynamicSharedMemorySize, SMEM_G64);

    // one-time per launch: weight transpose + split
    k_wsplit<<<dim3(24, 24, 36), dim3(32, 8)>>>(qkv_w,      pwq_hi, pwq_lo, HH, HH);
    k_wsplit<<<dim3(24, 24, 12), dim3(32, 8)>>>(attn_out_w, pwa_hi, pwa_lo, HH, HH);
    k_wsplit<<<dim3(96, 24, 12), dim3(32, 8)>>>(ffn_w1,     pw1_hi, pw1_lo, HH, FFF);
    k_wsplit<<<dim3(24, 96, 12), dim3(32, 8)>>>(ffn_w2,     pw2_hi, pw2_lo, FFF, HH);

    embed_ln_kernel<<<TOK, 256>>>(x, word_emb, pos_emb, type_emb, emb_ln_w, emb_ln_b);

    dim3 gQKV(HH / 128, TOK / 128, 3);   // (6,16,3)  = 288 CTAs
    dim3 gH64(HH / 64,  TOK / 128, 1);   // (12,16)   = 192 CTAs
    dim3 gF  (FFF / 128, TOK / 128, 1);  // (24,16)   = 384 CTAs
    dim3 gA  (NHH, BB);                  // (12,8)

    for (int l = 0; l < NLL; l++) {
        k_mma<128><<<gQKV, 256, SMEM_G128>>>(ph_hi, ph_lo,
            pwq_hi + (size_t)l*3*HH*HH, pwq_lo + (size_t)l*3*HH*HH,
            qkv_b + (size_t)l*3*HH,
            pqkv, nullptr, nullptr,
            HH, HH, 0, HH*HH, TOK*HH, HH);

        attn_kernel_v2<<<gA, 256, SMEM_ATTN>>>();

        k_mma<64><<<gH64, 256, SMEM_G64>>>(pcx_hi, pcx_lo,
            pwa_hi + (size_t)l*HH*HH, pwa_lo + (size_t)l*HH*HH,
            attn_out_b + (size_t)l*HH,
            pt1, nullptr, nullptr,
            HH, HH, 0, 0, 0, 0);
        resid_ln_kernel<<<TOK, 256>>>(pt1, attn_ln_w + (size_t)l*HH, attn_ln_b + (size_t)l*HH);

        k_mma<128><<<gF, 256, SMEM_G128>>>(ph_hi, ph_lo,
            pw1_hi + (size_t)l*HH*FFF, pw1_lo + (size_t)l*HH*FFF,
            ffn_b1 + (size_t)l*FFF,
            nullptr, pf_hi, pf_lo,
            FFF, HH, 1, 0, 0, 0);

        k_mma<64><<<gH64, 256, SMEM_G64>>>(pf_hi, pf_lo,
            pw2_hi + (size_t)l*FFF*HH, pw2_lo + (size_t)l*FFF*HH,
            ffn_b2 + (size_t)l*HH,
            pt1, nullptr, nullptr,
            HH, FFF, 0, 0, 0, 0);
        resid_ln_kernel<<<TOK, 256>>>(pt1, ffn_ln_w + (size_t)l*HH, ffn_ln_b + (size_t)l*HH);
    }

    emissions_kernel<<<TOK, 256>>>(cls_w, cls_b);
    crf_kernel<<<1, 128>>>(target, crf_start, crf_end, crf_trans, out);
}

// round 7
// speedup vs baseline: 5.3551x; 1.0674x over previous
#include <cuda_runtime.h>
#include <cuda_bf16.h>
#include <math.h>
#include <stdint.h>

#define BB   8
#define SS   256
#define HH   768
#define NLL  12
#define NHH  12
#define FFF  3072
#define CC   9
#define DHH  64
#define TOK  (BB*SS)   // 2048

// ================= scratch =================
__device__ float                         g_h   [TOK*HH];
__device__ __align__(256) __nv_bfloat16  g_h_hi[TOK*HH];
__device__ __align__(256) __nv_bfloat16  g_h_lo[TOK*HH];
__device__ __align__(256) float          g_qkv [3*TOK*HH];
__device__ __align__(256) __nv_bfloat16  g_cx_hi[TOK*HH];
__device__ __align__(256) __nv_bfloat16  g_cx_lo[TOK*HH];
__device__ __align__(256) float          g_t1  [TOK*HH];
__device__ __align__(256) __nv_bfloat16  g_f_hi[TOK*FFF];
__device__ __align__(256) __nv_bfloat16  g_f_lo[TOK*FFF];
__device__ float                         g_em  [TOK*CC];

__device__ __align__(256) __nv_bfloat16 w_qkv_hi[NLL*3*HH*HH];
__device__ __align__(256) __nv_bfloat16 w_qkv_lo[NLL*3*HH*HH];
__device__ __align__(256) __nv_bfloat16 w_ao_hi [NLL*HH*HH];
__device__ __align__(256) __nv_bfloat16 w_ao_lo [NLL*HH*HH];
__device__ __align__(256) __nv_bfloat16 w_f1_hi [NLL*HH*FFF];
__device__ __align__(256) __nv_bfloat16 w_f1_lo [NLL*HH*FFF];
__device__ __align__(256) __nv_bfloat16 w_f2_hi [NLL*FFF*HH];
__device__ __align__(256) __nv_bfloat16 w_f2_lo [NLL*FFF*HH];

// ================= low-level helpers =================
__device__ __forceinline__ void cpa16(uint32_t dst, const void* src) {
    asm volatile("cp.async.cg.shared.global [%0], [%1], 16;"
                 :: "r"(dst), "l"(src) : "memory");
}
#define CP_COMMIT() asm volatile("cp.async.commit_group;" ::: "memory")
#define CP_WAIT1()  asm volatile("cp.async.wait_group 1;" ::: "memory")
#define CP_WAIT0()  asm volatile("cp.async.wait_group 0;" ::: "memory")

__device__ __forceinline__ void ldm_x4(uint32_t* r, uint32_t a) {
    asm volatile("ldmatrix.sync.aligned.m8n8.x4.shared.b16 {%0,%1,%2,%3}, [%4];"
                 : "=r"(r[0]), "=r"(r[1]), "=r"(r[2]), "=r"(r[3]) : "r"(a));
}
__device__ __forceinline__ void mma16816(float* c, const uint32_t* a, const uint32_t* b) {
    asm volatile("mma.sync.aligned.m16n8k16.row.col.f32.bf16.bf16.f32 "
        "{%0,%1,%2,%3}, {%4,%5,%6,%7}, {%8,%9}, {%0,%1,%2,%3};"
        : "+f"(c[0]), "+f"(c[1]), "+f"(c[2]), "+f"(c[3])
        : "r"(a[0]), "r"(a[1]), "r"(a[2]), "r"(a[3]), "r"(b[0]), "r"(b[1]));
}

__device__ __forceinline__ float gelu_tanh(float v) {
    float c = 0.7978845608028654f * (v + 0.044715f * v * v * v);
    return 0.5f * v * (1.f + tanhf(c));
}
__device__ __forceinline__ void split_bf16(float v, __nv_bfloat16& h, __nv_bfloat16& l) {
    h = __float2bfloat16(v);
    l = __float2bfloat16(v - __bfloat162float(h));
}

// ================= weight transpose + split (64x64 tiles, float4) =================
// NOTE: row stride 68 floats = 272B (16B multiple) -> float4 stores stay aligned.
__global__ void k_wsplit64(const float* __restrict__ W,
                           __nv_bfloat16* __restrict__ hi,
                           __nv_bfloat16* __restrict__ lo,
                           int K, int N) {
    __shared__ float t[64][68];
    size_t moff = (size_t)blockIdx.z * K * N;
    int n0 = blockIdx.x * 64, k0 = blockIdx.y * 64;
    int tid = threadIdx.x;
#pragma unroll
    for (int i = 0; i < 4; i++) {
        int l4 = tid + i * 256;
        int r = l4 >> 4, c4 = (l4 & 15) * 4;
        *(float4*)&t[r][c4] = *(const float4*)&W[moff + (size_t)(k0 + r) * N + n0 + c4];
    }
    __syncthreads();
#pragma unroll
    for (int i = 0; i < 4; i++) {
        int l4 = tid + i * 256;
        int r = l4 >> 4, c4 = (l4 & 15) * 4;   // r: out row (n), c4: k offset
        float v0 = t[c4 + 0][r], v1 = t[c4 + 1][r], v2 = t[c4 + 2][r], v3 = t[c4 + 3][r];
        __nv_bfloat16 h0,l0,h1,l1,h2,l2,h3,l3;
        split_bf16(v0,h0,l0); split_bf16(v1,h1,l1);
        split_bf16(v2,h2,l2); split_bf16(v3,h3,l3);
        size_t o = moff + (size_t)(n0 + r) * K + k0 + c4;
        __nv_bfloat162 hh0 = __halves2bfloat162(h0,h1), hh1 = __halves2bfloat162(h2,h3);
        __nv_bfloat162 ll0 = __halves2bfloat162(l0,l1), ll1 = __halves2bfloat162(l2,l3);
        *(uint2*)(hi + o) = make_uint2(*(uint32_t*)&hh0, *(uint32_t*)&hh1);
        *(uint2*)(lo + o) = make_uint2(*(uint32_t*)&ll0, *(uint32_t*)&ll1);
    }
}

// ================= HMMA GEMM, 3-stage cp.async pipeline =================
#define PADK 40

template<int BN>
__global__ __launch_bounds__(256, 1)
void k_mma(const __nv_bfloat16* __restrict__ A_hi,
           const __nv_bfloat16* __restrict__ A_lo,
           const __nv_bfloat16* __restrict__ B_hi,
           const __nv_bfloat16* __restrict__ B_lo,
           const float* __restrict__ bias,
           float* __restrict__ Cf,
           __nv_bfloat16* __restrict__ Chi,
           __nv_bfloat16* __restrict__ Clo,
           int N, int K, int mode,
           int zW, int zC, int zB)
{
    constexpr int WMW = (BN == 128) ? 2 : 4;
    constexpr int WTM = 128 / WMW;
    constexpr int WTN = BN * WMW / 8;
    constexpr int MT  = WTM / 16;
    constexpr int ASZ = 128 * PADK;
    constexpr int BSZ = BN  * PADK;
    constexpr int STG = 2 * ASZ + 2 * BSZ;

    extern __shared__ __nv_bfloat16 smem_dyn[];
    uint32_t smb = (uint32_t)__cvta_generic_to_shared(smem_dyn);

    int tid = threadIdx.x, wid = tid >> 5, lane = tid & 31;
    int n0 = blockIdx.x * BN, m0 = blockIdx.y * 128, z = blockIdx.z;
    B_hi += (size_t)z * zW;  B_lo += (size_t)z * zW;
    bias += (size_t)z * zB;
    if (Cf) Cf += (size_t)z * zC;

    int wm = (wid % WMW) * WTM;
    int wn = (wid / WMW) * WTN;

    float acc[MT][4][4];
#pragma unroll
    for (int mt = 0; mt < MT; mt++)
#pragma unroll
        for (int nt = 0; nt < 4; nt++)
#pragma unroll
            for (int f = 0; f < 4; f++) acc[mt][nt][f] = 0.f;

    auto load_stage = [&](int s, int k0) {
        uint32_t base = smb + (uint32_t)(s * STG) * 2;
#pragma unroll
        for (int i = 0; i < 2; i++) {
            int idx = tid + i * 256;
            int r = idx >> 2, ch = idx & 3;
            const char* g0 = (const char*)(A_hi + (size_t)(m0 + r) * K + k0) + ch * 16;
            const char* g1 = (const char*)(A_lo + (size_t)(m0 + r) * K + k0) + ch * 16;
            cpa16(base + (uint32_t)(r * PADK) * 2 + ch * 16, g0);
            cpa16(base + (uint32_t)(ASZ + r * PADK) * 2 + ch * 16, g1);
        }
#pragma unroll
        for (int i = 0; i < (BN * 4) / 256; i++) {
            int idx = tid + i * 256;
            int r = idx >> 2, ch = idx & 3;
            const char* g0 = (const char*)(B_hi + (size_t)(n0 + r) * K + k0) + ch * 16;
            const char* g1 = (const char*)(B_lo + (size_t)(n0 + r) * K + k0) + ch * 16;
            cpa16(base + (uint32_t)(2 * ASZ + r * PADK) * 2 + ch * 16, g0);
            cpa16(base + (uint32_t)(2 * ASZ + BSZ + r * PADK) * 2 + ch * 16, g1);
        }
    };

    int nc = K / 32;
    load_stage(0, 0);
    CP_COMMIT();
    load_stage(1, 32);
    CP_COMMIT();

    uint32_t aRow = (uint32_t)(wm + (lane & 15));
    uint32_t aK   = (uint32_t)((lane >> 4) * 8);
    uint32_t bRow = (uint32_t)(wn + ((lane >> 4) & 1) * 8 + (lane & 7));
    uint32_t bK   = (uint32_t)(((lane >> 3) & 1) * 8);

    for (int c = 0; c < nc; c++) {
        int b = c % 3;
        if (c == nc - 1) { CP_WAIT0(); } else { CP_WAIT1(); }
        __syncthreads();
        if (c + 2 < nc) {
            load_stage((c + 2) % 3, (c + 2) * 32);
            CP_COMMIT();
        }

        uint32_t sbase = smb + (uint32_t)(b * STG) * 2;
#pragma unroll
        for (int k16 = 0; k16 < 2; k16++) {
            uint32_t ah[MT][4], al[MT][4];
#pragma unroll
            for (int mt = 0; mt < MT; mt++) {
                uint32_t off = ((aRow + mt * 16) * PADK + (uint32_t)(k16 * 16) + aK) * 2;
                ldm_x4(ah[mt], sbase + off);
                ldm_x4(al[mt], sbase + (uint32_t)ASZ * 2 + off);
            }
            uint32_t bh[2][4], bl[2][4];
#pragma unroll
            for (int np = 0; np < 2; np++) {
                uint32_t off = ((bRow + np * 16) * PADK + (uint32_t)(k16 * 16) + bK) * 2;
                ldm_x4(bh[np], sbase + (uint32_t)(2 * ASZ) * 2 + off);
                ldm_x4(bl[np], sbase + (uint32_t)(2 * ASZ + BSZ) * 2 + off);
            }
#pragma unroll
            for (int mt = 0; mt < MT; mt++)
#pragma unroll
                for (int nt = 0; nt < 4; nt++) {
                    const uint32_t* Bh = &bh[nt >> 1][(nt & 1) * 2];
                    const uint32_t* Bl = &bl[nt >> 1][(nt & 1) * 2];
                    mma16816(acc[mt][nt], ah[mt], Bh);
                    mma16816(acc[mt][nt], ah[mt], Bl);
                    mma16816(acc[mt][nt], al[mt], Bh);
                }
        }
    }

    int rbase = m0 + wm + (lane >> 2);
#pragma unroll
    for (int mt = 0; mt < MT; mt++) {
        int row = rbase + mt * 16;
#pragma unroll
        for (int nt = 0; nt < 4; nt++) {
            int col = n0 + wn + nt * 8 + (lane & 3) * 2;
            float b0 = bias[col], b1 = bias[col + 1];
            float v0 = acc[mt][nt][0] + b0;
            float v1 = acc[mt][nt][1] + b1;
            float v2 = acc[mt][nt][2] + b0;
            float v3 = acc[mt][nt][3] + b1;
            if (mode == 0) {
                *(float2*)(Cf + (size_t)row * N + col)       = make_float2(v0, v1);
                *(float2*)(Cf + (size_t)(row + 8) * N + col) = make_float2(v2, v3);
            } else {
                v0 = gelu_tanh(v0); v1 = gelu_tanh(v1);
                v2 = gelu_tanh(v2); v3 = gelu_tanh(v3);
                __nv_bfloat16 h0, l0, h1, l1;
                split_bf16(v0, h0, l0); split_bf16(v1, h1, l1);
                *(__nv_bfloat162*)(Chi + (size_t)row * N + col) = __halves2bfloat162(h0, h1);
                *(__nv_bfloat162*)(Clo + (size_t)row * N + col) = __halves2bfloat162(l0, l1);
                split_bf16(v2, h0, l0); split_bf16(v3, h1, l1);
                *(__nv_bfloat162*)(Chi + (size_t)(row + 8) * N + col) = __halves2bfloat162(h0, h1);
                *(__nv_bfloat162*)(Clo + (size_t)(row + 8) * N + col) = __halves2bfloat162(l0, l1);
            }
        }
    }
}

// ================= embed + LN (float4) =================
__global__ void embed_ln_kernel(const int* __restrict__ x,
                                const float* __restrict__ we,
                                const float* __restrict__ pe,
                                const float* __restrict__ te,
                                const float* __restrict__ lw,
                                const float* __restrict__ lb) {
    int t = blockIdx.x, s = t % SS, tid = threadIdx.x;
    int wid = x[t];
    bool act = tid < 192;
    float4 v4 = make_float4(0.f, 0.f, 0.f, 0.f);
    if (act) {
        float4 a = *(const float4*)&we[(size_t)wid * HH + tid * 4];
        float4 b = *(const float4*)&pe[s * HH + tid * 4];
        float4 c = *(const float4*)&te[tid * 4];
        v4 = make_float4(a.x+b.x+c.x, a.y+b.y+c.y, a.z+b.z+c.z, a.w+b.w+c.w);
    }
    float sum = v4.x + v4.y + v4.z + v4.w;
    float sq  = v4.x*v4.x + v4.y*v4.y + v4.z*v4.z + v4.w*v4.w;
    __shared__ float red[256], red2[256];
    red[tid] = sum; red2[tid] = sq; __syncthreads();
    for (int off = 128; off > 0; off >>= 1) {
        if (tid < off) { red[tid] += red[tid+off]; red2[tid] += red2[tid+off]; }
        __syncthreads();
    }
    float m = red[0] * (1.f/HH), var = red2[0] * (1.f/HH) - m*m;
    float rstd = rsqrtf(var + 1e-12f);
    if (act) {
        float4 w4 = *(const float4*)&lw[tid*4];
        float4 b4 = *(const float4*)&lb[tid*4];
        float o0 = (v4.x-m)*rstd*w4.x + b4.x;
        float o1 = (v4.y-m)*rstd*w4.y + b4.y;
        float o2 = (v4.z-m)*rstd*w4.z + b4.z;
        float o3 = (v4.w-m)*rstd*w4.w + b4.w;
        size_t idx = (size_t)t * HH + tid * 4;
        *(float4*)&g_h[idx] = make_float4(o0,o1,o2,o3);
        __nv_bfloat16 h0,l0,h1,l1,h2,l2,h3,l3;
        split_bf16(o0,h0,l0); split_bf16(o1,h1,l1);
        split_bf16(o2,h2,l2); split_bf16(o3,h3,l3);
        __nv_bfloat162 hh0=__halves2bfloat162(h0,h1), hh1=__halves2bfloat162(h2,h3);
        __nv_bfloat162 ll0=__halves2bfloat162(l0,l1), ll1=__halves2bfloat162(l2,l3);
        *(uint2*)(g_h_hi + idx) = make_uint2(*(uint32_t*)&hh0, *(uint32_t*)&hh1);
        *(uint2*)(g_h_lo + idx) = make_uint2(*(uint32_t*)&ll0, *(uint32_t*)&ll1);
    }
}

// ================= residual + LN (float4) =================
__global__ void resid_ln_kernel(const float* __restrict__ add,
                                const float* __restrict__ lw,
                                const float* __restrict__ lb) {
    int t = blockIdx.x, tid = threadIdx.x;
    bool act = tid < 192;
    float4 v4 = make_float4(0.f, 0.f, 0.f, 0.f);
    size_t idx = (size_t)t * HH + tid * 4;
    if (act) {
        float4 a = *(const float4*)&g_h[idx];
        float4 b = *(const float4*)&add[idx];
        v4 = make_float4(a.x+b.x, a.y+b.y, a.z+b.z, a.w+b.w);
    }
    float sum = v4.x + v4.y + v4.z + v4.w;
    float sq  = v4.x*v4.x + v4.y*v4.y + v4.z*v4.z + v4.w*v4.w;
    __shared__ float red[256], red2[256];
    red[tid] = sum; red2[tid] = sq; __syncthreads();
    for (int off = 128; off > 0; off >>= 1) {
        if (tid < off) { red[tid] += red[tid+off]; red2[tid] += red2[tid+off]; }
        __syncthreads();
    }
    float m = red[0] * (1.f/HH), var = red2[0] * (1.f/HH) - m*m;
    float rstd = rsqrtf(var + 1e-12f);
    if (act) {
        float4 w4 = *(const float4*)&lw[tid*4];
        float4 b4 = *(const float4*)&lb[tid*4];
        float o0 = (v4.x-m)*rstd*w4.x + b4.x;
        float o1 = (v4.y-m)*rstd*w4.y + b4.y;
        float o2 = (v4.z-m)*rstd*w4.z + b4.z;
        float o3 = (v4.w-m)*rstd*w4.w + b4.w;
        *(float4*)&g_h[idx] = make_float4(o0,o1,o2,o3);
        __nv_bfloat16 h0,l0,h1,l1,h2,l2,h3,l3;
        split_bf16(o0,h0,l0); split_bf16(o1,h1,l1);
        split_bf16(o2,h2,l2); split_bf16(o3,h3,l3);
        __nv_bfloat162 hh0=__halves2bfloat162(h0,h1), hh1=__halves2bfloat162(h2,h3);
        __nv_bfloat162 ll0=__halves2bfloat162(l0,l1), ll1=__halves2bfloat162(l2,l3);
        *(uint2*)(g_h_hi + idx) = make_uint2(*(uint32_t*)&hh0, *(uint32_t*)&hh1);
        *(uint2*)(g_h_lo + idx) = make_uint2(*(uint32_t*)&ll0, *(uint32_t*)&ll1);
    }
}

// ================= attention v3: vectorized smem access =================
__global__ void attn_kernel_v3() {
    extern __shared__ float sm[];
    float* Qs = sm;               // [256][64]
    float* KT = Qs + 256 * 64;    // [64][256]
    float* Vs = KT + 64 * 256;    // [256][64]
    float* Ps = Vs + 256 * 64;    // [32][256]

    const float* gq = g_qkv;
    const float* gk = g_qkv + (size_t)TOK * HH;
    const float* gv = g_qkv + 2 * (size_t)TOK * HH;

    int h = blockIdx.x, b = blockIdx.y;
    int tid = threadIdx.x, lane = tid & 31, w = tid >> 5;
    size_t base = (size_t)(b * SS) * HH + h * DHH;

    for (int i = tid; i < 256 * 16; i += 256) {
        int r = i >> 4, c4 = (i & 15) * 4;
        size_t g = base + (size_t)r * HH + c4;
        *(float4*)&Qs[r * 64 + c4] = *(const float4*)&gq[g];
        *(float4*)&Vs[r * 64 + c4] = *(const float4*)&gv[g];
        float4 k4 = *(const float4*)&gk[g];
        KT[(c4 + 0) * 256 + r] = k4.x;
        KT[(c4 + 1) * 256 + r] = k4.y;
        KT[(c4 + 2) * 256 + r] = k4.z;
        KT[(c4 + 3) * 256 + r] = k4.w;
    }
    __syncthreads();

    int lane8 = lane * 8;
    for (int pass = 0; pass < 4; pass++) {
        int qbase = pass * 64 + w * 8;
        float acc[8][8];
#pragma unroll
        for (int i = 0; i < 8; i++)
#pragma unroll
            for (int j = 0; j < 8; j++) acc[i][j] = 0.f;

        for (int d4 = 0; d4 < 64; d4 += 4) {
            float ka[4][8];
#pragma unroll
            for (int dd = 0; dd < 4; dd++) {
                float4 a = *(const float4*)&KT[(d4 + dd) * 256 + lane8];
                float4 bb = *(const float4*)&KT[(d4 + dd) * 256 + lane8 + 4];
                ka[dd][0]=a.x; ka[dd][1]=a.y; ka[dd][2]=a.z; ka[dd][3]=a.w;
                ka[dd][4]=bb.x; ka[dd][5]=bb.y; ka[dd][6]=bb.z; ka[dd][7]=bb.w;
            }
#pragma unroll
            for (int i = 0; i < 8; i++) {
                float4 q4 = *(const float4*)&Qs[(qbase + i) * 64 + d4];
                float qv[4] = {q4.x, q4.y, q4.z, q4.w};
#pragma unroll
                for (int dd = 0; dd < 4; dd++)
#pragma unroll
                    for (int j = 0; j < 8; j++)
                        acc[i][j] += qv[dd] * ka[dd][j];
            }
        }

        float inv_[8];
#pragma unroll
        for (int i = 0; i < 8; i++) {
            float m = -1e30f;
#pragma unroll
            for (int j = 0; j < 8; j++) m = fmaxf(m, acc[i][j]);
#pragma unroll
            for (int off = 16; off > 0; off >>= 1)
                m = fmaxf(m, __shfl_xor_sync(0xffffffffu, m, off));
            float s = 0.f;
#pragma unroll
            for (int j = 0; j < 8; j++) {
                acc[i][j] = __expf(0.125f * (acc[i][j] - m));
                s += acc[i][j];
            }
#pragma unroll
            for (int off = 16; off > 0; off >>= 1)
                s += __shfl_xor_sync(0xffffffffu, s, off);
            inv_[i] = 1.f / s;
        }

        int dql = (lane & 15) * 4, kh = lane >> 4;
#pragma unroll
        for (int chunk = 0; chunk < 2; chunk++) {
#pragma unroll
            for (int ii = 0; ii < 4; ii++) {
                int i = chunk * 4 + ii;
                float iv = inv_[i];
                *(float4*)&Ps[(w * 4 + ii) * 256 + lane8] =
                    make_float4(acc[i][0]*iv, acc[i][1]*iv, acc[i][2]*iv, acc[i][3]*iv);
                *(float4*)&Ps[(w * 4 + ii) * 256 + lane8 + 4] =
                    make_float4(acc[i][4]*iv, acc[i][5]*iv, acc[i][6]*iv, acc[i][7]*iv);
            }
            __syncwarp();

            float c[4][4];
#pragma unroll
            for (int ii = 0; ii < 4; ii++)
#pragma unroll
                for (int f = 0; f < 4; f++) c[ii][f] = 0.f;

            for (int kk = 0; kk < 128; kk++) {
                int k = kh * 128 + kk;
                float4 v4 = *(const float4*)&Vs[k * 64 + dql];
#pragma unroll
                for (int ii = 0; ii < 4; ii++) {
                    float p = Ps[(w * 4 + ii) * 256 + k];
                    c[ii][0] += p * v4.x;
                    c[ii][1] += p * v4.y;
                    c[ii][2] += p * v4.z;
                    c[ii][3] += p * v4.w;
                }
            }
#pragma unroll
            for (int ii = 0; ii < 4; ii++)
#pragma unroll
                for (int f = 0; f < 4; f++)
                    c[ii][f] += __shfl_xor_sync(0xffffffffu, c[ii][f], 16);

            if (lane < 16) {
#pragma unroll
                for (int ii = 0; ii < 4; ii++) {
                    int q = qbase + chunk * 4 + ii;
                    size_t idx = base + (size_t)q * HH + dql;
                    __nv_bfloat16 h0,l0,h1,l1,h2,l2,h3,l3;
                    split_bf16(c[ii][0],h0,l0); split_bf16(c[ii][1],h1,l1);
                    split_bf16(c[ii][2],h2,l2); split_bf16(c[ii][3],h3,l3);
                    __nv_bfloat162 hh0=__halves2bfloat162(h0,h1), hh1=__halves2bfloat162(h2,h3);
                    __nv_bfloat162 ll0=__halves2bfloat162(l0,l1), ll1=__halves2bfloat162(l2,l3);
                    *(uint2*)(g_cx_hi + idx) = make_uint2(*(uint32_t*)&hh0, *(uint32_t*)&hh1);
                    *(uint2*)(g_cx_lo + idx) = make_uint2(*(uint32_t*)&ll0, *(uint32_t*)&ll1);
                }
            }
            __syncwarp();
        }
    }
}

// ================= emissions =================
__global__ void emissions_kernel(const float* __restrict__ cw,
                                 const float* __restrict__ cb) {
    int t = blockIdx.x, tid = threadIdx.x;
    float part[CC];
#pragma unroll
    for (int c = 0; c < CC; c++) part[c] = 0.f;
    for (int k = tid; k < HH; k += 256) {
        float hv = g_h[(size_t)t * HH + k];
        const float* wr = cw + (size_t)k * CC;
#pragma unroll
        for (int c = 0; c < CC; c++) part[c] += hv * wr[c];
    }
#pragma unroll
    for (int c = 0; c < CC; c++)
        for (int off = 16; off > 0; off >>= 1)
            part[c] += __shfl_down_sync(0xffffffffu, part[c], off);

    __shared__ float wred[8][CC];
    int lane = tid & 31, w = tid >> 5;
    if (lane == 0)
#pragma unroll
        for (int c = 0; c < CC; c++) wred[w][c] = part[c];
    __syncthreads();
    if (tid < CC) {
        float s = cb[tid];
#pragma unroll
        for (int ww = 0; ww < 8; ww++) s += wred[ww][tid];
        g_em[(size_t)t * CC + tid] = s;
    }
}

// ================= CRF =================
__global__ void crf_kernel(const int* __restrict__ target,
                           const float* __restrict__ cstart,
                           const float* __restrict__ cend,
                           const float* __restrict__ ctrans,
                           float* __restrict__ out) {
    __shared__ float alpha[BB][CC];
    __shared__ float trans[CC][CC];
    __shared__ float den[BB], num[BB];
    int tid = threadIdx.x;

    if (tid < CC * CC) trans[tid / CC][tid % CC] = ctrans[tid];
    __syncthreads();

    int b = tid / CC, j = tid % CC;
    bool act = (tid < BB * CC);
    if (act) alpha[b][j] = cstart[j] + g_em[(size_t)(b * SS) * CC + j];
    __syncthreads();

    for (int s = 1; s < SS; s++) {
        float nv = 0.f;
        if (act) {
            float m = -1e30f;
#pragma unroll
            for (int i = 0; i < CC; i++) m = fmaxf(m, alpha[b][i] + trans[i][j]);
            float sum = 0.f;
#pragma unroll
            for (int i = 0; i < CC; i++) sum += __expf(alpha[b][i] + trans[i][j] - m);
            nv = m + __logf(sum) + g_em[(size_t)(b * SS + s) * CC + j];
            if (!(target[b * SS + s] > -1)) nv = alpha[b][j];
        }
        __syncthreads();
        if (act) alpha[b][j] = nv;
        __syncthreads();
    }

    if (act && j == 0) {
        float m = -1e30f;
#pragma unroll
        for (int jj = 0; jj < CC; jj++) m = fmaxf(m, alpha[b][jj] + cend[jj]);
        float sum = 0.f;
#pragma unroll
        for (int jj = 0; jj < CC; jj++) sum += __expf(alpha[b][jj] + cend[jj] - m);
        den[b] = m + __logf(sum);

        const int* tb = target + b * SS;
        int cnt = 0;
        for (int s = 0; s < SS; s++) cnt += (tb[s] > -1) ? 1 : 0;
        int send = cnt - 1;
        int t0 = tb[0] < 0 ? 0 : tb[0];
        float nu = cstart[t0] + g_em[(size_t)(b * SS) * CC + t0];
        for (int s = 1; s < SS; s++) {
            int ts = tb[s], tp = tb[s - 1];
            float mk = (ts > -1) ? 1.f : 0.f;
            int tsc = ts < 0 ? 0 : ts, tpc = tp < 0 ? 0 : tp;
            nu += mk * (trans[tpc][tsc] + g_em[(size_t)(b * SS + s) * CC + tsc]);
        }
        int last = tb[send < 0 ? 0 : send];
        nu += cend[last < 0 ? 0 : last];
        num[b] = nu;
    }
    __syncthreads();
    if (tid == 0) {
        float L = 0.f;
        for (int bb = 0; bb < BB; bb++) L += num[bb] - den[bb];
        out[0] = -L / BB;
    }
}

// ================= launch =================
extern "C" void kernel_launch(void* const* d_in, const int* in_sizes, int n_in,
                              void* d_out, int out_size) {
    const int*   x          = (const int*)  d_in[0];
    const int*   target     = (const int*)  d_in[1];
    const float* word_emb   = (const float*)d_in[2];
    const float* pos_emb    = (const float*)d_in[3];
    const float* type_emb   = (const float*)d_in[4];
    const float* emb_ln_w   = (const float*)d_in[5];
    const float* emb_ln_b   = (const float*)d_in[6];
    const float* qkv_w      = (const float*)d_in[7];
    const float* qkv_b      = (const float*)d_in[8];
    const float* attn_out_w = (const float*)d_in[9];
    const float* attn_out_b = (const float*)d_in[10];
    const float* attn_ln_w  = (const float*)d_in[11];
    const float* attn_ln_b  = (const float*)d_in[12];
    const float* ffn_w1     = (const float*)d_in[13];
    const float* ffn_b1     = (const float*)d_in[14];
    const float* ffn_w2     = (const float*)d_in[15];
    const float* ffn_b2     = (const float*)d_in[16];
    const float* ffn_ln_w   = (const float*)d_in[17];
    const float* ffn_ln_b   = (const float*)d_in[18];
    const float* cls_w      = (const float*)d_in[19];
    const float* cls_b      = (const float*)d_in[20];
    const float* crf_start  = (const float*)d_in[21];
    const float* crf_end    = (const float*)d_in[22];
    const float* crf_trans  = (const float*)d_in[23];
    float* out = (float*)d_out;

    float *pt1, *pqkv;
    __nv_bfloat16 *ph_hi, *ph_lo, *pcx_hi, *pcx_lo, *pf_hi, *pf_lo;
    __nv_bfloat16 *pwq_hi, *pwq_lo, *pwa_hi, *pwa_lo, *pw1_hi, *pw1_lo, *pw2_hi, *pw2_lo;
    cudaGetSymbolAddress((void**)&pt1,    g_t1);
    cudaGetSymbolAddress((void**)&pqkv,   g_qkv);
    cudaGetSymbolAddress((void**)&ph_hi,  g_h_hi);
    cudaGetSymbolAddress((void**)&ph_lo,  g_h_lo);
    cudaGetSymbolAddress((void**)&pcx_hi, g_cx_hi);
    cudaGetSymbolAddress((void**)&pcx_lo, g_cx_lo);
    cudaGetSymbolAddress((void**)&pf_hi,  g_f_hi);
    cudaGetSymbolAddress((void**)&pf_lo,  g_f_lo);
    cudaGetSymbolAddress((void**)&pwq_hi, w_qkv_hi);
    cudaGetSymbolAddress((void**)&pwq_lo, w_qkv_lo);
    cudaGetSymbolAddress((void**)&pwa_hi, w_ao_hi);
    cudaGetSymbolAddress((void**)&pwa_lo, w_ao_lo);
    cudaGetSymbolAddress((void**)&pw1_hi, w_f1_hi);
    cudaGetSymbolAddress((void**)&pw1_lo, w_f1_lo);
    cudaGetSymbolAddress((void**)&pw2_hi, w_f2_hi);
    cudaGetSymbolAddress((void**)&pw2_lo, w_f2_lo);

    const int SMEM_ATTN = (256*64 + 64*256 + 256*64 + 32*256) * 4;  // 229376
    const int SMEM_G128 = 3 * (2*128*PADK + 2*128*PADK) * 2;        // 122880
    const int SMEM_G64  = 3 * (2*128*PADK + 2*64*PADK) * 2;         // 92160
    cudaFuncSetAttribute(attn_kernel_v3,
                         cudaFuncAttributeMaxDynamicSharedMemorySize, SMEM_ATTN);
    cudaFuncSetAttribute(k_mma<128>,
                         cudaFuncAttributeMaxDynamicSharedMemorySize, SMEM_G128);
    cudaFuncSetAttribute(k_mma<64>,
                         cudaFuncAttributeMaxDynamicSharedMemorySize, SMEM_G64);

    k_wsplit64<<<dim3(12, 12, 36), 256>>>(qkv_w,      pwq_hi, pwq_lo, HH, HH);
    k_wsplit64<<<dim3(12, 12, 12), 256>>>(attn_out_w, pwa_hi, pwa_lo, HH, HH);
    k_wsplit64<<<dim3(48, 12, 12), 256>>>(ffn_w1,     pw1_hi, pw1_lo, HH, FFF);
    k_wsplit64<<<dim3(12, 48, 12), 256>>>(ffn_w2,     pw2_hi, pw2_lo, FFF, HH);

    embed_ln_kernel<<<TOK, 256>>>(x, word_emb, pos_emb, type_emb, emb_ln_w, emb_ln_b);

    dim3 gQKV(HH / 128, TOK / 128, 3);
    dim3 gH64(HH / 64,  TOK / 128, 1);
    dim3 gF  (FFF / 128, TOK / 128, 1);
    dim3 gA  (NHH, BB);

    for (int l = 0; l < NLL; l++) {
        k_mma<128><<<gQKV, 256, SMEM_G128>>>(ph_hi, ph_lo,
            pwq_hi + (size_t)l*3*HH*HH, pwq_lo + (size_t)l*3*HH*HH,
            qkv_b + (size_t)l*3*HH,
            pqkv, nullptr, nullptr,
            HH, HH, 0, HH*HH, TOK*HH, HH);

        attn_kernel_v3<<<gA, 256, SMEM_ATTN>>>();

        k_mma<64><<<gH64, 256, SMEM_G64>>>(pcx_hi, pcx_lo,
            pwa_hi + (size_t)l*HH*HH, pwa_lo + (size_t)l*HH*HH,
            attn_out_b + (size_t)l*HH,
            pt1, nullptr, nullptr,
            HH, HH, 0, 0, 0, 0);
        resid_ln_kernel<<<TOK, 256>>>(pt1, attn_ln_w + (size_t)l*HH, attn_ln_b + (size_t)l*HH);

        k_mma<128><<<gF, 256, SMEM_G128>>>(ph_hi, ph_lo,
            pw1_hi + (size_t)l*HH*FFF, pw1_lo + (size_t)l*HH*FFF,
            ffn_b1 + (size_t)l*FFF,
            nullptr, pf_hi, pf_lo,
            FFF, HH, 1, 0, 0, 0);

        k_mma<64><<<gH64, 256, SMEM_G64>>>(pf_hi, pf_lo,
            pw2_hi + (size_t)l*FFF*HH, pw2_lo + (size_t)l*FFF*HH,
            ffn_b2 + (size_t)l*HH,
            pt1, nullptr, nullptr,
            HH, FFF, 0, 0, 0, 0);
        resid_ln_kernel<<<TOK, 256>>>(pt1, ffn_ln_w + (size_t)l*HH, ffn_ln_b + (size_t)l*HH);
    }

    emissions_kernel<<<TOK, 256>>>(cls_w, cls_b);
    crf_kernel<<<1, 128>>>(target, crf_start, crf_end, crf_trans, out);
}

// round 8
// speedup vs baseline: 5.4483x; 1.0174x over previous
#include <cuda_runtime.h>
#include <cuda_bf16.h>
#include <math.h>
#include <stdint.h>

#define BB   8
#define SS   256
#define HH   768
#define NLL  12
#define NHH  12
#define FFF  3072
#define CC   9
#define DHH  64
#define TOK  (BB*SS)   // 2048

// ================= scratch =================
__device__ float                         g_h   [TOK*HH];
__device__ __align__(256) __nv_bfloat16  g_h_hi[TOK*HH];
__device__ __align__(256) __nv_bfloat16  g_h_lo[TOK*HH];
__device__ __align__(256) float          g_qkv [3*TOK*HH];
__device__ __align__(256) __nv_bfloat16  g_cx_hi[TOK*HH];
__device__ __align__(256) __nv_bfloat16  g_cx_lo[TOK*HH];
__device__ __align__(256) float          g_t1  [TOK*HH];
__device__ __align__(256) __nv_bfloat16  g_f_hi[TOK*FFF];
__device__ __align__(256) __nv_bfloat16  g_f_lo[TOK*FFF];
__device__ float                         g_em  [TOK*CC];

__device__ __align__(256) __nv_bfloat16 w_qkv_hi[NLL*3*HH*HH];
__device__ __align__(256) __nv_bfloat16 w_qkv_lo[NLL*3*HH*HH];
__device__ __align__(256) __nv_bfloat16 w_ao_hi [NLL*HH*HH];
__device__ __align__(256) __nv_bfloat16 w_ao_lo [NLL*HH*HH];
__device__ __align__(256) __nv_bfloat16 w_f1_hi [NLL*HH*FFF];
__device__ __align__(256) __nv_bfloat16 w_f1_lo [NLL*HH*FFF];
__device__ __align__(256) __nv_bfloat16 w_f2_hi [NLL*FFF*HH];
__device__ __align__(256) __nv_bfloat16 w_f2_lo [NLL*FFF*HH];

// ================= low-level helpers =================
__device__ __forceinline__ void cpa16(uint32_t dst, const void* src) {
    asm volatile("cp.async.cg.shared.global [%0], [%1], 16;"
                 :: "r"(dst), "l"(src) : "memory");
}
#define CP_COMMIT() asm volatile("cp.async.commit_group;" ::: "memory")
#define CP_WAIT1()  asm volatile("cp.async.wait_group 1;" ::: "memory")
#define CP_WAIT0()  asm volatile("cp.async.wait_group 0;" ::: "memory")

__device__ __forceinline__ void ldm_x4(uint32_t* r, uint32_t a) {
    asm volatile("ldmatrix.sync.aligned.m8n8.x4.shared.b16 {%0,%1,%2,%3}, [%4];"
                 : "=r"(r[0]), "=r"(r[1]), "=r"(r[2]), "=r"(r[3]) : "r"(a));
}
__device__ __forceinline__ void mma16816(float* c, const uint32_t* a, const uint32_t* b) {
    asm volatile("mma.sync.aligned.m16n8k16.row.col.f32.bf16.bf16.f32 "
        "{%0,%1,%2,%3}, {%4,%5,%6,%7}, {%8,%9}, {%0,%1,%2,%3};"
        : "+f"(c[0]), "+f"(c[1]), "+f"(c[2]), "+f"(c[3])
        : "r"(a[0]), "r"(a[1]), "r"(a[2]), "r"(a[3]), "r"(b[0]), "r"(b[1]));
}

__device__ __forceinline__ float gelu_tanh(float v) {
    float c = 0.7978845608028654f * (v + 0.044715f * v * v * v);
    return 0.5f * v * (1.f + tanhf(c));
}
__device__ __forceinline__ void split_bf16(float v, __nv_bfloat16& h, __nv_bfloat16& l) {
    h = __float2bfloat16(v);
    l = __float2bfloat16(v - __bfloat162float(h));
}

// ================= weight transpose + split =================
__global__ void k_wsplit64(const float* __restrict__ W,
                           __nv_bfloat16* __restrict__ hi,
                           __nv_bfloat16* __restrict__ lo,
                           int K, int N) {
    __shared__ float t[64][68];
    size_t moff = (size_t)blockIdx.z * K * N;
    int n0 = blockIdx.x * 64, k0 = blockIdx.y * 64;
    int tid = threadIdx.x;
#pragma unroll
    for (int i = 0; i < 4; i++) {
        int l4 = tid + i * 256;
        int r = l4 >> 4, c4 = (l4 & 15) * 4;
        *(float4*)&t[r][c4] = *(const float4*)&W[moff + (size_t)(k0 + r) * N + n0 + c4];
    }
    __syncthreads();
#pragma unroll
    for (int i = 0; i < 4; i++) {
        int l4 = tid + i * 256;
        int r = l4 >> 4, c4 = (l4 & 15) * 4;
        float v0 = t[c4 + 0][r], v1 = t[c4 + 1][r], v2 = t[c4 + 2][r], v3 = t[c4 + 3][r];
        __nv_bfloat16 h0,l0,h1,l1,h2,l2,h3,l3;
        split_bf16(v0,h0,l0); split_bf16(v1,h1,l1);
        split_bf16(v2,h2,l2); split_bf16(v3,h3,l3);
        size_t o = moff + (size_t)(n0 + r) * K + k0 + c4;
        __nv_bfloat162 hh0 = __halves2bfloat162(h0,h1), hh1 = __halves2bfloat162(h2,h3);
        __nv_bfloat162 ll0 = __halves2bfloat162(l0,l1), ll1 = __halves2bfloat162(l2,l3);
        *(uint2*)(hi + o) = make_uint2(*(uint32_t*)&hh0, *(uint32_t*)&hh1);
        *(uint2*)(lo + o) = make_uint2(*(uint32_t*)&ll0, *(uint32_t*)&ll1);
    }
}

// ================= HMMA GEMM, 2-stage pipeline, 2 CTAs/SM =================
#define PADK 40

template<int BN>
__global__ __launch_bounds__(256, 2)
void k_mma(const __nv_bfloat16* __restrict__ A_hi,
           const __nv_bfloat16* __restrict__ A_lo,
           const __nv_bfloat16* __restrict__ B_hi,
           const __nv_bfloat16* __restrict__ B_lo,
           const float* __restrict__ bias,
           float* __restrict__ Cf,
           __nv_bfloat16* __restrict__ Chi,
           __nv_bfloat16* __restrict__ Clo,
           int N, int K, int mode,
           int zW, int zC, int zB)
{
    constexpr int WMW = (BN == 128) ? 2 : 4;
    constexpr int WTM = 128 / WMW;
    constexpr int WTN = BN * WMW / 8;
    constexpr int MT  = WTM / 16;
    constexpr int ASZ = 128 * PADK;
    constexpr int BSZ = BN  * PADK;
    constexpr int STG = 2 * ASZ + 2 * BSZ;

    extern __shared__ __nv_bfloat16 smem_dyn[];
    uint32_t smb = (uint32_t)__cvta_generic_to_shared(smem_dyn);

    int tid = threadIdx.x, wid = tid >> 5, lane = tid & 31;
    int n0 = blockIdx.x * BN, m0 = blockIdx.y * 128, z = blockIdx.z;
    B_hi += (size_t)z * zW;  B_lo += (size_t)z * zW;
    bias += (size_t)z * zB;
    if (Cf) Cf += (size_t)z * zC;

    int wm = (wid % WMW) * WTM;
    int wn = (wid / WMW) * WTN;

    float acc[MT][4][4];
#pragma unroll
    for (int mt = 0; mt < MT; mt++)
#pragma unroll
        for (int nt = 0; nt < 4; nt++)
#pragma unroll
            for (int f = 0; f < 4; f++) acc[mt][nt][f] = 0.f;

    auto load_stage = [&](int s, int k0) {
        uint32_t base = smb + (uint32_t)(s * STG) * 2;
#pragma unroll
        for (int i = 0; i < 2; i++) {
            int idx = tid + i * 256;
            int r = idx >> 2, ch = idx & 3;
            const char* g0 = (const char*)(A_hi + (size_t)(m0 + r) * K + k0) + ch * 16;
            const char* g1 = (const char*)(A_lo + (size_t)(m0 + r) * K + k0) + ch * 16;
            cpa16(base + (uint32_t)(r * PADK) * 2 + ch * 16, g0);
            cpa16(base + (uint32_t)(ASZ + r * PADK) * 2 + ch * 16, g1);
        }
#pragma unroll
        for (int i = 0; i < (BN * 4) / 256; i++) {
            int idx = tid + i * 256;
            int r = idx >> 2, ch = idx & 3;
            const char* g0 = (const char*)(B_hi + (size_t)(n0 + r) * K + k0) + ch * 16;
            const char* g1 = (const char*)(B_lo + (size_t)(n0 + r) * K + k0) + ch * 16;
            cpa16(base + (uint32_t)(2 * ASZ + r * PADK) * 2 + ch * 16, g0);
            cpa16(base + (uint32_t)(2 * ASZ + BSZ + r * PADK) * 2 + ch * 16, g1);
        }
    };

    int nc = K / 32;
    load_stage(0, 0);
    CP_COMMIT();
    load_stage(1, 32);
    CP_COMMIT();

    uint32_t aRow = (uint32_t)(wm + (lane & 15));
    uint32_t aK   = (uint32_t)((lane >> 4) * 8);
    uint32_t bRow = (uint32_t)(wn + ((lane >> 4) & 1) * 8 + (lane & 7));
    uint32_t bK   = (uint32_t)(((lane >> 3) & 1) * 8);

    for (int c = 0; c < nc; c++) {
        int b = c & 1;
        if (c == nc - 1) { CP_WAIT0(); } else { CP_WAIT1(); }
        __syncthreads();

        uint32_t sbase = smb + (uint32_t)(b * STG) * 2;
#pragma unroll
        for (int k16 = 0; k16 < 2; k16++) {
            uint32_t bh[2][4], bl[2][4];
#pragma unroll
            for (int np = 0; np < 2; np++) {
                uint32_t off = ((bRow + np * 16) * PADK + (uint32_t)(k16 * 16) + bK) * 2;
                ldm_x4(bh[np], sbase + (uint32_t)(2 * ASZ) * 2 + off);
                ldm_x4(bl[np], sbase + (uint32_t)(2 * ASZ + BSZ) * 2 + off);
            }
#pragma unroll
            for (int mt = 0; mt < MT; mt++) {
                uint32_t ah[4], al[4];
                uint32_t off = ((aRow + mt * 16) * PADK + (uint32_t)(k16 * 16) + aK) * 2;
                ldm_x4(ah, sbase + off);
                ldm_x4(al, sbase + (uint32_t)ASZ * 2 + off);
#pragma unroll
                for (int nt = 0; nt < 4; nt++) {
                    const uint32_t* Bh = &bh[nt >> 1][(nt & 1) * 2];
                    const uint32_t* Bl = &bl[nt >> 1][(nt & 1) * 2];
                    mma16816(acc[mt][nt], ah, Bh);
                    mma16816(acc[mt][nt], ah, Bl);
                    mma16816(acc[mt][nt], al, Bh);
                }
            }
        }

        if (c + 2 < nc) {
            __syncthreads();               // all warps done reading stage b
            load_stage(b, (c + 2) * 32);
            CP_COMMIT();
        }
    }

    int rbase = m0 + wm + (lane >> 2);
#pragma unroll
    for (int mt = 0; mt < MT; mt++) {
        int row = rbase + mt * 16;
#pragma unroll
        for (int nt = 0; nt < 4; nt++) {
            int col = n0 + wn + nt * 8 + (lane & 3) * 2;
            float b0 = bias[col], b1 = bias[col + 1];
            float v0 = acc[mt][nt][0] + b0;
            float v1 = acc[mt][nt][1] + b1;
            float v2 = acc[mt][nt][2] + b0;
            float v3 = acc[mt][nt][3] + b1;
            if (mode == 0) {
                *(float2*)(Cf + (size_t)row * N + col)       = make_float2(v0, v1);
                *(float2*)(Cf + (size_t)(row + 8) * N + col) = make_float2(v2, v3);
            } else {
                v0 = gelu_tanh(v0); v1 = gelu_tanh(v1);
                v2 = gelu_tanh(v2); v3 = gelu_tanh(v3);
                __nv_bfloat16 h0, l0, h1, l1;
                split_bf16(v0, h0, l0); split_bf16(v1, h1, l1);
                *(__nv_bfloat162*)(Chi + (size_t)row * N + col) = __halves2bfloat162(h0, h1);
                *(__nv_bfloat162*)(Clo + (size_t)row * N + col) = __halves2bfloat162(l0, l1);
                split_bf16(v2, h0, l0); split_bf16(v3, h1, l1);
                *(__nv_bfloat162*)(Chi + (size_t)(row + 8) * N + col) = __halves2bfloat162(h0, h1);
                *(__nv_bfloat162*)(Clo + (size_t)(row + 8) * N + col) = __halves2bfloat162(l0, l1);
            }
        }
    }
}

// ================= embed + LN (float4) =================
__global__ void embed_ln_kernel(const int* __restrict__ x,
                                const float* __restrict__ we,
                                const float* __restrict__ pe,
                                const float* __restrict__ te,
                                const float* __restrict__ lw,
                                const float* __restrict__ lb) {
    int t = blockIdx.x, s = t % SS, tid = threadIdx.x;
    int wid = x[t];
    bool act = tid < 192;
    float4 v4 = make_float4(0.f, 0.f, 0.f, 0.f);
    if (act) {
        float4 a = *(const float4*)&we[(size_t)wid * HH + tid * 4];
        float4 b = *(const float4*)&pe[s * HH + tid * 4];
        float4 c = *(const float4*)&te[tid * 4];
        v4 = make_float4(a.x+b.x+c.x, a.y+b.y+c.y, a.z+b.z+c.z, a.w+b.w+c.w);
    }
    float sum = v4.x + v4.y + v4.z + v4.w;
    float sq  = v4.x*v4.x + v4.y*v4.y + v4.z*v4.z + v4.w*v4.w;
    __shared__ float red[256], red2[256];
    red[tid] = sum; red2[tid] = sq; __syncthreads();
    for (int off = 128; off > 0; off >>= 1) {
        if (tid < off) { red[tid] += red[tid+off]; red2[tid] += red2[tid+off]; }
        __syncthreads();
    }
    float m = red[0] * (1.f/HH), var = red2[0] * (1.f/HH) - m*m;
    float rstd = rsqrtf(var + 1e-12f);
    if (act) {
        float4 w4 = *(const float4*)&lw[tid*4];
        float4 b4 = *(const float4*)&lb[tid*4];
        float o0 = (v4.x-m)*rstd*w4.x + b4.x;
        float o1 = (v4.y-m)*rstd*w4.y + b4.y;
        float o2 = (v4.z-m)*rstd*w4.z + b4.z;
        float o3 = (v4.w-m)*rstd*w4.w + b4.w;
        size_t idx = (size_t)t * HH + tid * 4;
        *(float4*)&g_h[idx] = make_float4(o0,o1,o2,o3);
        __nv_bfloat16 h0,l0,h1,l1,h2,l2,h3,l3;
        split_bf16(o0,h0,l0); split_bf16(o1,h1,l1);
        split_bf16(o2,h2,l2); split_bf16(o3,h3,l3);
        __nv_bfloat162 hh0=__halves2bfloat162(h0,h1), hh1=__halves2bfloat162(h2,h3);
        __nv_bfloat162 ll0=__halves2bfloat162(l0,l1), ll1=__halves2bfloat162(l2,l3);
        *(uint2*)(g_h_hi + idx) = make_uint2(*(uint32_t*)&hh0, *(uint32_t*)&hh1);
        *(uint2*)(g_h_lo + idx) = make_uint2(*(uint32_t*)&ll0, *(uint32_t*)&ll1);
    }
}

// ================= residual + LN (float4) =================
__global__ void resid_ln_kernel(const float* __restrict__ add,
                                const float* __restrict__ lw,
                                const float* __restrict__ lb) {
    int t = blockIdx.x, tid = threadIdx.x;
    bool act = tid < 192;
    float4 v4 = make_float4(0.f, 0.f, 0.f, 0.f);
    size_t idx = (size_t)t * HH + tid * 4;
    if (act) {
        float4 a = *(const float4*)&g_h[idx];
        float4 b = *(const float4*)&add[idx];
        v4 = make_float4(a.x+b.x, a.y+b.y, a.z+b.z, a.w+b.w);
    }
    float sum = v4.x + v4.y + v4.z + v4.w;
    float sq  = v4.x*v4.x + v4.y*v4.y + v4.z*v4.z + v4.w*v4.w;
    __shared__ float red[256], red2[256];
    red[tid] = sum; red2[tid] = sq; __syncthreads();
    for (int off = 128; off > 0; off >>= 1) {
        if (tid < off) { red[tid] += red[tid+off]; red2[tid] += red2[tid+off]; }
        __syncthreads();
    }
    float m = red[0] * (1.f/HH), var = red2[0] * (1.f/HH) - m*m;
    float rstd = rsqrtf(var + 1e-12f);
    if (act) {
        float4 w4 = *(const float4*)&lw[tid*4];
        float4 b4 = *(const float4*)&lb[tid*4];
        float o0 = (v4.x-m)*rstd*w4.x + b4.x;
        float o1 = (v4.y-m)*rstd*w4.y + b4.y;
        float o2 = (v4.z-m)*rstd*w4.z + b4.z;
        float o3 = (v4.w-m)*rstd*w4.w + b4.w;
        *(float4*)&g_h[idx] = make_float4(o0,o1,o2,o3);
        __nv_bfloat16 h0,l0,h1,l1,h2,l2,h3,l3;
        split_bf16(o0,h0,l0); split_bf16(o1,h1,l1);
        split_bf16(o2,h2,l2); split_bf16(o3,h3,l3);
        __nv_bfloat162 hh0=__halves2bfloat162(h0,h1), hh1=__halves2bfloat162(h2,h3);
        __nv_bfloat162 ll0=__halves2bfloat162(l0,l1), ll1=__halves2bfloat162(l2,l3);
        *(uint2*)(g_h_hi + idx) = make_uint2(*(uint32_t*)&hh0, *(uint32_t*)&hh1);
        *(uint2*)(g_h_lo + idx) = make_uint2(*(uint32_t*)&ll0, *(uint32_t*)&ll1);
    }
}

// ================= attention v4: q-split across 2 CTAs per head =================
__global__ void attn_kernel_v4() {
    extern __shared__ float sm[];
    float* Qs = sm;               // [128][64]
    float* KT = Qs + 128 * 64;    // [64][256]
    float* Vs = KT + 64 * 256;    // [256][64]
    float* Ps = Vs + 256 * 64;    // [32][256]

    const float* gq = g_qkv;
    const float* gk = g_qkv + (size_t)TOK * HH;
    const float* gv = g_qkv + 2 * (size_t)TOK * HH;

    int h = blockIdx.x, b = blockIdx.y, qh = blockIdx.z;
    int tid = threadIdx.x, lane = tid & 31, w = tid >> 5;
    size_t base = (size_t)(b * SS) * HH + h * DHH;
    int qoff = qh * 128;

    // Q: 128 rows for this half
    for (int i = tid; i < 128 * 16; i += 256) {
        int r = i >> 4, c4 = (i & 15) * 4;
        *(float4*)&Qs[r * 64 + c4] =
            *(const float4*)&gq[base + (size_t)(qoff + r) * HH + c4];
    }
    // K (transposed), V: full 256 rows
    for (int i = tid; i < 256 * 16; i += 256) {
        int r = i >> 4, c4 = (i & 15) * 4;
        size_t g = base + (size_t)r * HH + c4;
        *(float4*)&Vs[r * 64 + c4] = *(const float4*)&gv[g];
        float4 k4 = *(const float4*)&gk[g];
        KT[(c4 + 0) * 256 + r] = k4.x;
        KT[(c4 + 1) * 256 + r] = k4.y;
        KT[(c4 + 2) * 256 + r] = k4.z;
        KT[(c4 + 3) * 256 + r] = k4.w;
    }
    __syncthreads();

    int lane8 = lane * 8;
    for (int pass = 0; pass < 2; pass++) {
        int qbase = pass * 64 + w * 8;      // row in Qs
        float acc[8][8];
#pragma unroll
        for (int i = 0; i < 8; i++)
#pragma unroll
            for (int j = 0; j < 8; j++) acc[i][j] = 0.f;

        for (int d4 = 0; d4 < 64; d4 += 4) {
            float ka[4][8];
#pragma unroll
            for (int dd = 0; dd < 4; dd++) {
                float4 a = *(const float4*)&KT[(d4 + dd) * 256 + lane8];
                float4 bb = *(const float4*)&KT[(d4 + dd) * 256 + lane8 + 4];
                ka[dd][0]=a.x; ka[dd][1]=a.y; ka[dd][2]=a.z; ka[dd][3]=a.w;
                ka[dd][4]=bb.x; ka[dd][5]=bb.y; ka[dd][6]=bb.z; ka[dd][7]=bb.w;
            }
#pragma unroll
            for (int i = 0; i < 8; i++) {
                float4 q4 = *(const float4*)&Qs[(qbase + i) * 64 + d4];
                float qv[4] = {q4.x, q4.y, q4.z, q4.w};
#pragma unroll
                for (int dd = 0; dd < 4; dd++)
#pragma unroll
                    for (int j = 0; j < 8; j++)
                        acc[i][j] += qv[dd] * ka[dd][j];
            }
        }

        float inv_[8];
#pragma unroll
        for (int i = 0; i < 8; i++) {
            float m = -1e30f;
#pragma unroll
            for (int j = 0; j < 8; j++) m = fmaxf(m, acc[i][j]);
#pragma unroll
            for (int off = 16; off > 0; off >>= 1)
                m = fmaxf(m, __shfl_xor_sync(0xffffffffu, m, off));
            float s = 0.f;
#pragma unroll
            for (int j = 0; j < 8; j++) {
                acc[i][j] = __expf(0.125f * (acc[i][j] - m));
                s += acc[i][j];
            }
#pragma unroll
            for (int off = 16; off > 0; off >>= 1)
                s += __shfl_xor_sync(0xffffffffu, s, off);
            inv_[i] = 1.f / s;
        }

        int dql = (lane & 15) * 4, kh = lane >> 4;
#pragma unroll
        for (int chunk = 0; chunk < 2; chunk++) {
#pragma unroll
            for (int ii = 0; ii < 4; ii++) {
                int i = chunk * 4 + ii;
                float iv = inv_[i];
                *(float4*)&Ps[(w * 4 + ii) * 256 + lane8] =
                    make_float4(acc[i][0]*iv, acc[i][1]*iv, acc[i][2]*iv, acc[i][3]*iv);
                *(float4*)&Ps[(w * 4 + ii) * 256 + lane8 + 4] =
                    make_float4(acc[i][4]*iv, acc[i][5]*iv, acc[i][6]*iv, acc[i][7]*iv);
            }
            __syncwarp();

            float c[4][4];
#pragma unroll
            for (int ii = 0; ii < 4; ii++)
#pragma unroll
                for (int f = 0; f < 4; f++) c[ii][f] = 0.f;

            for (int kk = 0; kk < 128; kk++) {
                int k = kh * 128 + kk;
                float4 v4 = *(const float4*)&Vs[k * 64 + dql];
#pragma unroll
                for (int ii = 0; ii < 4; ii++) {
                    float p = Ps[(w * 4 + ii) * 256 + k];
                    c[ii][0] += p * v4.x;
                    c[ii][1] += p * v4.y;
                    c[ii][2] += p * v4.z;
                    c[ii][3] += p * v4.w;
                }
            }
#pragma unroll
            for (int ii = 0; ii < 4; ii++)
#pragma unroll
                for (int f = 0; f < 4; f++)
                    c[ii][f] += __shfl_xor_sync(0xffffffffu, c[ii][f], 16);

            if (lane < 16) {
#pragma unroll
                for (int ii = 0; ii < 4; ii++) {
                    int q = qoff + qbase + chunk * 4 + ii;
                    size_t idx = base + (size_t)q * HH + dql;
                    __nv_bfloat16 h0,l0,h1,l1,h2,l2,h3,l3;
                    split_bf16(c[ii][0],h0,l0); split_bf16(c[ii][1],h1,l1);
                    split_bf16(c[ii][2],h2,l2); split_bf16(c[ii][3],h3,l3);
                    __nv_bfloat162 hh0=__halves2bfloat162(h0,h1), hh1=__halves2bfloat162(h2,h3);
                    __nv_bfloat162 ll0=__halves2bfloat162(l0,l1), ll1=__halves2bfloat162(l2,l3);
                    *(uint2*)(g_cx_hi + idx) = make_uint2(*(uint32_t*)&hh0, *(uint32_t*)&hh1);
                    *(uint2*)(g_cx_lo + idx) = make_uint2(*(uint32_t*)&ll0, *(uint32_t*)&ll1);
                }
            }
            __syncwarp();
        }
    }
}

// ================= emissions =================
__global__ void emissions_kernel(const float* __restrict__ cw,
                                 const float* __restrict__ cb) {
    int t = blockIdx.x, tid = threadIdx.x;
    float part[CC];
#pragma unroll
    for (int c = 0; c < CC; c++) part[c] = 0.f;
    for (int k = tid; k < HH; k += 256) {
        float hv = g_h[(size_t)t * HH + k];
        const float* wr = cw + (size_t)k * CC;
#pragma unroll
        for (int c = 0; c < CC; c++) part[c] += hv * wr[c];
    }
#pragma unroll
    for (int c = 0; c < CC; c++)
        for (int off = 16; off > 0; off >>= 1)
            part[c] += __shfl_down_sync(0xffffffffu, part[c], off);

    __shared__ float wred[8][CC];
    int lane = tid & 31, w = tid >> 5;
    if (lane == 0)
#pragma unroll
        for (int c = 0; c < CC; c++) wred[w][c] = part[c];
    __syncthreads();
    if (tid < CC) {
        float s = cb[tid];
#pragma unroll
        for (int ww = 0; ww < 8; ww++) s += wred[ww][tid];
        g_em[(size_t)t * CC + tid] = s;
    }
}

// ================= CRF =================
__global__ void crf_kernel(const int* __restrict__ target,
                           const float* __restrict__ cstart,
                           const float* __restrict__ cend,
                           const float* __restrict__ ctrans,
                           float* __restrict__ out) {
    __shared__ float alpha[BB][CC];
    __shared__ float trans[CC][CC];
    __shared__ float den[BB], num[BB];
    int tid = threadIdx.x;

    if (tid < CC * CC) trans[tid / CC][tid % CC] = ctrans[tid];
    __syncthreads();

    int b = tid / CC, j = tid % CC;
    bool act = (tid < BB * CC);
    if (act) alpha[b][j] = cstart[j] + g_em[(size_t)(b * SS) * CC + j];
    __syncthreads();

    for (int s = 1; s < SS; s++) {
        float nv = 0.f;
        if (act) {
            float m = -1e30f;
#pragma unroll
            for (int i = 0; i < CC; i++) m = fmaxf(m, alpha[b][i] + trans[i][j]);
            float sum = 0.f;
#pragma unroll
            for (int i = 0; i < CC; i++) sum += __expf(alpha[b][i] + trans[i][j] - m);
            nv = m + __logf(sum) + g_em[(size_t)(b * SS + s) * CC + j];
            if (!(target[b * SS + s] > -1)) nv = alpha[b][j];
        }
        __syncthreads();
        if (act) alpha[b][j] = nv;
        __syncthreads();
    }

    if (act && j == 0) {
        float m = -1e30f;
#pragma unroll
        for (int jj = 0; jj < CC; jj++) m = fmaxf(m, alpha[b][jj] + cend[jj]);
        float sum = 0.f;
#pragma unroll
        for (int jj = 0; jj < CC; jj++) sum += __expf(alpha[b][jj] + cend[jj] - m);
        den[b] = m + __logf(sum);

        const int* tb = target + b * SS;
        int cnt = 0;
        for (int s = 0; s < SS; s++) cnt += (tb[s] > -1) ? 1 : 0;
        int send = cnt - 1;
        int t0 = tb[0] < 0 ? 0 : tb[0];
        float nu = cstart[t0] + g_em[(size_t)(b * SS) * CC + t0];
        for (int s = 1; s < SS; s++) {
            int ts = tb[s], tp = tb[s - 1];
            float mk = (ts > -1) ? 1.f : 0.f;
            int tsc = ts < 0 ? 0 : ts, tpc = tp < 0 ? 0 : tp;
            nu += mk * (trans[tpc][tsc] + g_em[(size_t)(b * SS + s) * CC + tsc]);
        }
        int last = tb[send < 0 ? 0 : send];
        nu += cend[last < 0 ? 0 : last];
        num[b] = nu;
    }
    __syncthreads();
    if (tid == 0) {
        float L = 0.f;
        for (int bb = 0; bb < BB; bb++) L += num[bb] - den[bb];
        out[0] = -L / BB;
    }
}

// ================= launch =================
extern "C" void kernel_launch(void* const* d_in, const int* in_sizes, int n_in,
                              void* d_out, int out_size) {
    const int*   x          = (const int*)  d_in[0];
    const int*   target     = (const int*)  d_in[1];
    const float* word_emb   = (const float*)d_in[2];
    const float* pos_emb    = (const float*)d_in[3];
    const float* type_emb   = (const float*)d_in[4];
    const float* emb_ln_w   = (const float*)d_in[5];
    const float* emb_ln_b   = (const float*)d_in[6];
    const float* qkv_w      = (const float*)d_in[7];
    const float* qkv_b      = (const float*)d_in[8];
    const float* attn_out_w = (const float*)d_in[9];
    const float* attn_out_b = (const float*)d_in[10];
    const float* attn_ln_w  = (const float*)d_in[11];
    const float* attn_ln_b  = (const float*)d_in[12];
    const float* ffn_w1     = (const float*)d_in[13];
    const float* ffn_b1     = (const float*)d_in[14];
    const float* ffn_w2     = (const float*)d_in[15];
    const float* ffn_b2     = (const float*)d_in[16];
    const float* ffn_ln_w   = (const float*)d_in[17];
    const float* ffn_ln_b   = (const float*)d_in[18];
    const float* cls_w      = (const float*)d_in[19];
    const float* cls_b      = (const float*)d_in[20];
    const float* crf_start  = (const float*)d_in[21];
    const float* crf_end    = (const float*)d_in[22];
    const float* crf_trans  = (const float*)d_in[23];
    float* out = (float*)d_out;

    float *pt1, *pqkv;
    __nv_bfloat16 *ph_hi, *ph_lo, *pcx_hi, *pcx_lo, *pf_hi, *pf_lo;
    __nv_bfloat16 *pwq_hi, *pwq_lo, *pwa_hi, *pwa_lo, *pw1_hi, *pw1_lo, *pw2_hi, *pw2_lo;
    cudaGetSymbolAddress((void**)&pt1,    g_t1);
    cudaGetSymbolAddress((void**)&pqkv,   g_qkv);
    cudaGetSymbolAddress((void**)&ph_hi,  g_h_hi);
    cudaGetSymbolAddress((void**)&ph_lo,  g_h_lo);
    cudaGetSymbolAddress((void**)&pcx_hi, g_cx_hi);
    cudaGetSymbolAddress((void**)&pcx_lo, g_cx_lo);
    cudaGetSymbolAddress((void**)&pf_hi,  g_f_hi);
    cudaGetSymbolAddress((void**)&pf_lo,  g_f_lo);
    cudaGetSymbolAddress((void**)&pwq_hi, w_qkv_hi);
    cudaGetSymbolAddress((void**)&pwq_lo, w_qkv_lo);
    cudaGetSymbolAddress((void**)&pwa_hi, w_ao_hi);
    cudaGetSymbolAddress((void**)&pwa_lo, w_ao_lo);
    cudaGetSymbolAddress((void**)&pw1_hi, w_f1_hi);
    cudaGetSymbolAddress((void**)&pw1_lo, w_f1_lo);
    cudaGetSymbolAddress((void**)&pw2_hi, w_f2_hi);
    cudaGetSymbolAddress((void**)&pw2_lo, w_f2_lo);

    const int SMEM_ATTN = (128*64 + 64*256 + 256*64 + 32*256) * 4;  // 196608
    const int SMEM_G128 = 2 * (2*128*PADK + 2*128*PADK) * 2;        // 81920
    const int SMEM_G64  = 2 * (2*128*PADK + 2*64*PADK) * 2;         // 61440
    cudaFuncSetAttribute(attn_kernel_v4,
                         cudaFuncAttributeMaxDynamicSharedMemorySize, SMEM_ATTN);
    cudaFuncSetAttribute(k_mma<128>,
                         cudaFuncAttributeMaxDynamicSharedMemorySize, SMEM_G128);
    cudaFuncSetAttribute(k_mma<64>,
                         cudaFuncAttributeMaxDynamicSharedMemorySize, SMEM_G64);

    k_wsplit64<<<dim3(12, 12, 36), 256>>>(qkv_w,      pwq_hi, pwq_lo, HH, HH);
    k_wsplit64<<<dim3(12, 12, 12), 256>>>(attn_out_w, pwa_hi, pwa_lo, HH, HH);
    k_wsplit64<<<dim3(48, 12, 12), 256>>>(ffn_w1,     pw1_hi, pw1_lo, HH, FFF);
    k_wsplit64<<<dim3(12, 48, 12), 256>>>(ffn_w2,     pw2_hi, pw2_lo, FFF, HH);

    embed_ln_kernel<<<TOK, 256>>>(x, word_emb, pos_emb, type_emb, emb_ln_w, emb_ln_b);

    dim3 gQKV(HH / 128, TOK / 128, 3);
    dim3 gH64(HH / 64,  TOK / 128, 1);
    dim3 gF  (FFF / 128, TOK / 128, 1);
    dim3 gA  (NHH, BB, 2);

    for (int l = 0; l < NLL; l++) {
        k_mma<128><<<gQKV, 256, SMEM_G128>>>(ph_hi, ph_lo,
            pwq_hi + (size_t)l*3*HH*HH, pwq_lo + (size_t)l*3*HH*HH,
            qkv_b + (size_t)l*3*HH,
            pqkv, nullptr, nullptr,
            HH, HH, 0, HH*HH, TOK*HH, HH);

        attn_kernel_v4<<<gA, 256, SMEM_ATTN>>>();

        k_mma<64><<<gH64, 256, SMEM_G64>>>(pcx_hi, pcx_lo,
            pwa_hi + (size_t)l*HH*HH, pwa_lo + (size_t)l*HH*HH,
            attn_out_b + (size_t)l*HH,
            pt1, nullptr, nullptr,
            HH, HH, 0, 0, 0, 0);
        resid_ln_kernel<<<TOK, 256>>>(pt1, attn_ln_w + (size_t)l*HH, attn_ln_b + (size_t)l*HH);

        k_mma<128><<<gF, 256, SMEM_G128>>>(ph_hi, ph_lo,
            pw1_hi + (size_t)l*HH*FFF, pw1_lo + (size_t)l*HH*FFF,
            ffn_b1 + (size_t)l*FFF,
            nullptr, pf_hi, pf_lo,
            FFF, HH, 1, 0, 0, 0);

        k_mma<64><<<gH64, 256, SMEM_G64>>>(pf_hi, pf_lo,
            pw2_hi + (size_t)l*FFF*HH, pw2_lo + (size_t)l*FFF*HH,
            ffn_b2 + (size_t)l*HH,
            pt1, nullptr, nullptr,
            HH, FFF, 0, 0, 0, 0);
        resid_ln_kernel<<<TOK, 256>>>(pt1, ffn_ln_w + (size_t)l*HH, ffn_ln_b + (size_t)l*HH);
    }

    emissions_kernel<<<TOK, 256>>>(cls_w, cls_b);
    crf_kernel<<<1, 128>>>(target, crf_start, crf_end, crf_trans, out);
}